// round 2
// baseline (speedup 1.0000x reference)
#include <cuda_runtime.h>
#include <math_constants.h>

// Problem constants
#define NN 56
#define HW 3136          // 56*56
#define NB 32            // batch
#define CI 64
#define CO 128
#define OB 4096          // CO*NB
#define IB 2048          // CI*NB
#define OI 8192          // CO*CI

// ---------------- scratch (device globals; no runtime allocation allowed) ----
__device__ __align__(16) float2 g_F [HW];                  // F[j*56+k] = e^{-2pi i jk/56}
__device__ __align__(16) float2 g_Kt[(size_t)HW * OI];     // [f][o*64+i]      206 MB
__device__ __align__(16) float2 g_Xf[(size_t)HW * IB];     // [f][i*32+b]       51 MB
__device__ __align__(16) float2 g_Yf[(size_t)HW * OB];     // [f][o*32+b]      103 MB
__device__ __align__(16) float2 g_Z [(size_t)HW * OB];     // [u*56+w][o*32+b] 103 MB
__device__ __align__(16) float  g_Y2[(size_t)HW * OB];     // [h*56+w][o*32+b]  51 MB

// ---------------- 0) twiddle init -------------------------------------------
__global__ void k_init_F() {
    int idx = blockIdx.x * blockDim.x + threadIdx.x;
    if (idx < HW) {
        int j = idx / NN, k = idx % NN;
        int m = (j * k) % NN;                       // exact angle reduction
        float ang = -2.0f * CUDART_PI_F * (float)m / (float)NN;
        float s, c;
        sincosf(ang, &s, &c);
        g_F[idx] = make_float2(c, s);
    }
}

// ---------------- 1) kernel transpose: [oi][f] (2 planes) -> float2 [f][oi] --
__global__ void k_transpose_K(const float* __restrict__ kr, const float* __restrict__ ki) {
    __shared__ float2 tile[32][33];
    int f0  = blockIdx.x * 32;
    int oi0 = blockIdx.y * 32;
    int tx = threadIdx.x, ty = threadIdx.y;
#pragma unroll
    for (int k = 0; k < 4; k++) {
        int oi = oi0 + ty + k * 8;
        size_t src = (size_t)oi * HW + f0 + tx;
        tile[ty + k * 8][tx] = make_float2(kr[src], ki[src]);
    }
    __syncthreads();
#pragma unroll
    for (int k = 0; k < 4; k++) {
        int f = f0 + ty + k * 8;
        g_Kt[(size_t)f * OI + oi0 + tx] = tile[tx][ty + k * 8];
    }
}

// ---------------- 2) forward fft2 per (b,i): Xf = F * x * F ------------------
// one CTA per (b,i); x plane + F + intermediate all in SMEM
__global__ void k_fwd_fft(const float* __restrict__ x) {
    extern __shared__ char smem[];
    float*  xs = (float*)smem;                         // [3136]
    float2* Fs = (float2*)(smem + HW * sizeof(float)); // [3136]
    float2* A1 = Fs + HW;                              // [56][57] padded

    int bi = blockIdx.x;                 // b*64 + i
    int b  = bi / CI, ci = bi % CI;
    int tid = threadIdx.x;

    for (int t = tid; t < HW; t += 256) {
        Fs[t] = g_F[t];
        xs[t] = x[(size_t)bi * HW + t];
    }
    __syncthreads();

    // stage a: A1[h,v] = sum_w x[h,w] * F[w,v]   (real * complex)
    for (int item = tid; item < HW; item += 256) {
        int h = item / NN, v = item % NN;
        float ar = 0.f, ai = 0.f;
        const float* xr = xs + h * NN;
#pragma unroll 8
        for (int w = 0; w < NN; w++) {
            float  xv = xr[w];
            float2 fv = Fs[w * NN + v];
            ar += xv * fv.x;
            ai += xv * fv.y;
        }
        A1[h * 57 + v] = make_float2(ar, ai);
    }
    __syncthreads();

    // stage b: Xf[u,v] = sum_h F[u,h] * A1[h,v]  (complex * complex)
    int col = ci * NB + b;
    for (int item = tid; item < HW; item += 256) {
        int u = item / NN, v = item % NN;
        float cr = 0.f, cim = 0.f;
#pragma unroll 8
        for (int h = 0; h < NN; h++) {
            float2 fv = Fs[u * NN + h];
            float2 av = A1[h * 57 + v];
            cr  += fv.x * av.x - fv.y * av.y;
            cim += fv.x * av.y + fv.y * av.x;
        }
        g_Xf[(size_t)item * IB + col] = make_float2(cr, cim);
    }
}

// ---------------- 3) per-frequency complex GEMM: Yf[o,b] = sum_i K[o,i]X[i,b]
__global__ void k_einsum() {
    __shared__ __align__(16) float2 Ksm[CO * 16];   // [o][ii]
    __shared__ __align__(16) float2 Xsm[16 * NB];   // [ii][b]
    int f   = blockIdx.x;
    int tid = threadIdx.x;
    int b0  = (tid & 15) * 2;     // 2 consecutive b per thread
    int og  = tid >> 4;           // o = og + 16*j, j=0..7

    float2 acc[8][2];
#pragma unroll
    for (int j = 0; j < 8; j++) {
        acc[j][0] = make_float2(0.f, 0.f);
        acc[j][1] = make_float2(0.f, 0.f);
    }

    const float2* Kf = g_Kt + (size_t)f * OI;
    const float2* Xf = g_Xf + (size_t)f * IB;

    for (int ic = 0; ic < 4; ic++) {              // i chunks of 16
#pragma unroll
        for (int t = tid; t < 2048; t += 256) {
            int o = t >> 4, ii = t & 15;
            Ksm[t] = Kf[o * CI + ic * 16 + ii];
        }
#pragma unroll
        for (int t = tid; t < 512; t += 256)
            Xsm[t] = Xf[ic * 512 + t];
        __syncthreads();

#pragma unroll
        for (int ii = 0; ii < 16; ii++) {
            float4 xv = *(const float4*)(&Xsm[ii * NB + b0]);   // 2 complex
#pragma unroll
            for (int j = 0; j < 8; j++) {
                float2 kv = Ksm[(og + 16 * j) * 16 + ii];
                acc[j][0].x += kv.x * xv.x - kv.y * xv.y;
                acc[j][0].y += kv.x * xv.y + kv.y * xv.x;
                acc[j][1].x += kv.x * xv.z - kv.y * xv.w;
                acc[j][1].y += kv.x * xv.w + kv.y * xv.z;
            }
        }
        __syncthreads();
    }

    float2* Yf = g_Yf + (size_t)f * OB;
#pragma unroll
    for (int j = 0; j < 8; j++) {
        int o = og + 16 * j;
        float4 st = make_float4(acc[j][0].x, acc[j][0].y, acc[j][1].x, acc[j][1].y);
        *(float4*)(&Yf[o * NB + b0]) = st;
    }
}

// ---------------- 4) inverse over v: Z[u,w,ob] = sum_v Yf[u,v,ob]*conjF[w,v] -
__global__ void k_ifft_v() {
    extern __shared__ char smem[];
    float2* Fc  = (float2*)smem;      // conj(F), 3136
    float2* Ysm = Fc + HW;            // [56][64]
    int u   = blockIdx.y;
    int obt = blockIdx.x;             // 64 tiles of 64
    int tid = threadIdx.x;
    int wg  = tid >> 6;               // 4 w-groups of 14
    int obl = tid & 63;

    for (int t = tid; t < HW; t += 256) {
        float2 f = g_F[t];
        Fc[t] = make_float2(f.x, -f.y);
    }
    for (int t = tid; t < NN * 64; t += 256) {
        int v = t >> 6, oo = t & 63;
        Ysm[t] = g_Yf[(size_t)(u * NN + v) * OB + obt * 64 + oo];
    }
    __syncthreads();

    float2 acc[14];
#pragma unroll
    for (int wi = 0; wi < 14; wi++) acc[wi] = make_float2(0.f, 0.f);

#pragma unroll 4
    for (int v = 0; v < NN; v++) {
        float2 y = Ysm[v * 64 + obl];
#pragma unroll
        for (int wi = 0; wi < 14; wi++) {
            float2 fc = Fc[(wg * 14 + wi) * NN + v];
            acc[wi].x += fc.x * y.x - fc.y * y.y;
            acc[wi].y += fc.x * y.y + fc.y * y.x;
        }
    }
    int ob = obt * 64 + obl;
#pragma unroll
    for (int wi = 0; wi < 14; wi++)
        g_Z[(size_t)(u * NN + wg * 14 + wi) * OB + ob] = acc[wi];
}

// ---------------- 5) inverse over u (real part only), scale 1/N^2 -----------
__global__ void k_ifft_u() {
    extern __shared__ char smem[];
    float2* Fs  = (float2*)smem;      // F, 3136
    float2* Zsm = Fs + HW;            // [56(u)][64]
    int w   = blockIdx.y;
    int obt = blockIdx.x;
    int tid = threadIdx.x;
    int hg  = tid >> 6;
    int obl = tid & 63;

    for (int t = tid; t < HW; t += 256) Fs[t] = g_F[t];
    for (int t = tid; t < NN * 64; t += 256) {
        int uu = t >> 6, oo = t & 63;
        Zsm[t] = g_Z[(size_t)(uu * NN + w) * OB + obt * 64 + oo];
    }
    __syncthreads();

    float acc[14];
#pragma unroll
    for (int hi = 0; hi < 14; hi++) acc[hi] = 0.f;

#pragma unroll 4
    for (int u = 0; u < NN; u++) {
        float2 z = Zsm[u * 64 + obl];
#pragma unroll
        for (int hi = 0; hi < 14; hi++) {
            float2 f = Fs[(hg * 14 + hi) * NN + u];
            // Re(conjF * Z) = Fr*Zr + Fi*Zi
            acc[hi] += f.x * z.x + f.y * z.y;
        }
    }
    const float s = 1.0f / (float)HW;
    int ob = obt * 64 + obl;
#pragma unroll
    for (int hi = 0; hi < 14; hi++)
        g_Y2[(size_t)((hg * 14 + hi) * NN + w) * OB + ob] = acc[hi] * s;
}

// ---------------- 6) final transpose [hw][ob] -> [b][o][hw] + bias ----------
__global__ void k_out(const float* __restrict__ bias, float* __restrict__ out) {
    __shared__ float tile[32][33];
    int hw0 = blockIdx.x * 32;
    int ob0 = blockIdx.y * 32;
    int tx = threadIdx.x, ty = threadIdx.y;
#pragma unroll
    for (int k = 0; k < 4; k++)
        tile[ty + k * 8][tx] = g_Y2[(size_t)(hw0 + ty + k * 8) * OB + ob0 + tx];
    __syncthreads();
#pragma unroll
    for (int k = 0; k < 4; k++) {
        int ob = ob0 + ty + k * 8;
        int o = ob >> 5, b = ob & 31;       // ob = o*32 + b
        out[(size_t)(b * CO + o) * HW + hw0 + tx] = tile[tx][ty + k * 8] + bias[o];
    }
}

// ---------------- launch -----------------------------------------------------
extern "C" void kernel_launch(void* const* d_in, const int* in_sizes, int n_in,
                              void* d_out, int out_size) {
    const float* x    = (const float*)d_in[0];   // [32,64,56,56]
    const float* kr   = (const float*)d_in[1];   // [128,64,56,56]
    const float* ki   = (const float*)d_in[2];   // [128,64,56,56]
    const float* bias = (const float*)d_in[3];   // [128]
    float* out = (float*)d_out;                  // [32,128,56,56]

    const int smem_fwd = HW * (int)sizeof(float) + (HW + 56 * 57) * (int)sizeof(float2); // 63168
    const int smem_inv = (HW + NN * 64) * (int)sizeof(float2);                           // 53760
    cudaFuncSetAttribute(k_fwd_fft, cudaFuncAttributeMaxDynamicSharedMemorySize, smem_fwd);
    cudaFuncSetAttribute(k_ifft_v, cudaFuncAttributeMaxDynamicSharedMemorySize, smem_inv);
    cudaFuncSetAttribute(k_ifft_u, cudaFuncAttributeMaxDynamicSharedMemorySize, smem_inv);

    k_init_F<<<(HW + 255) / 256, 256>>>();
    k_transpose_K<<<dim3(HW / 32, OI / 32), dim3(32, 8)>>>(kr, ki);
    k_fwd_fft<<<IB, 256, smem_fwd>>>(x);
    k_einsum<<<HW, 256>>>();
    k_ifft_v<<<dim3(64, NN), 256, smem_inv>>>();
    k_ifft_u<<<dim3(64, NN), 256, smem_inv>>>();
    k_out<<<dim3(HW / 32, OB / 32), dim3(32, 8)>>>(bias, out);
}

// round 3
// speedup vs baseline: 1.6415x; 1.6415x over previous
#include <cuda_runtime.h>
#include <math_constants.h>

// Problem constants
#define NN 56
#define HW 3136          // 56*56
#define NV 29            // rfft columns: v in [0,28]
#define NF (NN*NV)       // 1624 retained frequencies
#define NB 32            // batch
#define CI 64
#define CO 128
#define OB 4096          // CO*NB
#define IB 2048          // CI*NB
#define OI 8192          // CO*CI

// ---------------- scratch (device globals; no runtime allocation allowed) ----
__device__ __align__(16) float2 g_F [HW];                  // F[j*56+k] = e^{-2pi i jk/56}
__device__ __align__(16) float2 g_Kt[(size_t)NF * OI];     // [u*29+v][o*64+i]   106 MB
__device__ __align__(16) float2 g_Xf[(size_t)NF * IB];     // [u*29+v][i*32+b]    27 MB
__device__ __align__(16) float2 g_Yf[(size_t)NF * OB];     // [u*29+v][o*32+b]    53 MB
__device__ __align__(16) float2 g_Z [(size_t)NF * OB];     // [h*29+v][o*32+b]    53 MB
__device__ __align__(16) float  g_Y2[(size_t)HW * OB];     // [h*56+w][o*32+b]    51 MB

// ---------------- 0) twiddle init -------------------------------------------
__global__ void k_init_F() {
    int idx = blockIdx.x * blockDim.x + threadIdx.x;
    if (idx < HW) {
        int j = idx / NN, k = idx % NN;
        int m = (j * k) % NN;                       // exact angle reduction
        float ang = -2.0f * CUDART_PI_F * (float)m / (float)NN;
        float s, c;
        sincosf(ang, &s, &c);
        g_F[idx] = make_float2(c, s);
    }
}

// ------- 1) kernel transpose: [oi][f=u*56+v, v<29] -> float2 [u*29+v][oi] ----
__global__ void k_transpose_K(const float* __restrict__ kr, const float* __restrict__ ki) {
    __shared__ float2 tile[32][33];
    int fi0 = blockIdx.x * 32;            // fidx tile (fidx = u*29+v)
    int oi0 = blockIdx.y * 32;
    int tx = threadIdx.x, ty = threadIdx.y;
    int fi = fi0 + tx;
    int valid = fi < NF;
    int u = fi / NV, v = fi - u * NV;
    int fsrc = u * NN + v;                // source column in full spectrum
#pragma unroll
    for (int k = 0; k < 4; k++) {
        int oi = oi0 + ty + k * 8;
        if (valid) {
            size_t src = (size_t)oi * HW + fsrc;
            tile[ty + k * 8][tx] = make_float2(kr[src], ki[src]);
        }
    }
    __syncthreads();
#pragma unroll
    for (int k = 0; k < 4; k++) {
        int f = fi0 + ty + k * 8;
        if (f < NF)
            g_Kt[(size_t)f * OI + oi0 + tx] = tile[tx][ty + k * 8];
    }
}

// ------- 2) forward rfft2 per (b,i): Xf[u,v] for v in [0,29) -----------------
__global__ void k_fwd_fft(const float* __restrict__ x) {
    extern __shared__ char smem[];
    float*  xs = (float*)smem;                         // [3136]
    float2* Fs = (float2*)(smem + HW * sizeof(float)); // [3136]
    float2* A1 = Fs + HW;                              // [56][30] padded

    int bi = blockIdx.x;                 // b*64 + i
    int b  = bi / CI, ci = bi % CI;
    int tid = threadIdx.x;

    for (int t = tid; t < HW; t += 256) {
        Fs[t] = g_F[t];
        xs[t] = x[(size_t)bi * HW + t];
    }
    __syncthreads();

    // stage a: A1[h,v] = sum_w x[h,w] * F[w,v]   (real * complex), v < 29
    for (int item = tid; item < NN * NV; item += 256) {
        int h = item / NV, v = item - h * NV;
        float ar = 0.f, ai = 0.f;
        const float* xr = xs + h * NN;
#pragma unroll 8
        for (int w = 0; w < NN; w++) {
            float  xv = xr[w];
            float2 fv = Fs[w * NN + v];
            ar += xv * fv.x;
            ai += xv * fv.y;
        }
        A1[h * 30 + v] = make_float2(ar, ai);
    }
    __syncthreads();

    // stage b: Xf[u,v] = sum_h F[u,h] * A1[h,v]  (complex * complex)
    int col = ci * NB + b;
    for (int item = tid; item < NN * NV; item += 256) {
        int u = item / NV, v = item - u * NV;
        float cr = 0.f, cim = 0.f;
#pragma unroll 8
        for (int h = 0; h < NN; h++) {
            float2 fv = Fs[u * NN + h];
            float2 av = A1[h * 30 + v];
            cr  += fv.x * av.x - fv.y * av.y;
            cim += fv.x * av.y + fv.y * av.x;
        }
        g_Xf[(size_t)item * IB + col] = make_float2(cr, cim);
    }
}

// ------- 3) per-frequency complex GEMM: Yf[o,b] = sum_i K[o,i]X[i,b] ---------
__global__ void k_einsum() {
    __shared__ __align__(16) float2 Ksm[CO * 16];   // [o][ii]
    __shared__ __align__(16) float2 Xsm[16 * NB];   // [ii][b]
    int f   = blockIdx.x;                 // fidx
    int tid = threadIdx.x;
    int b0  = (tid & 15) * 2;     // 2 consecutive b per thread
    int og  = tid >> 4;           // o = og + 16*j, j=0..7

    float2 acc[8][2];
#pragma unroll
    for (int j = 0; j < 8; j++) {
        acc[j][0] = make_float2(0.f, 0.f);
        acc[j][1] = make_float2(0.f, 0.f);
    }

    const float2* Kf = g_Kt + (size_t)f * OI;
    const float2* Xf = g_Xf + (size_t)f * IB;

    for (int ic = 0; ic < 4; ic++) {              // i chunks of 16
#pragma unroll
        for (int t = tid; t < 2048; t += 256) {
            int o = t >> 4, ii = t & 15;
            Ksm[t] = Kf[o * CI + ic * 16 + ii];
        }
#pragma unroll
        for (int t = tid; t < 512; t += 256)
            Xsm[t] = Xf[ic * 512 + t];
        __syncthreads();

#pragma unroll
        for (int ii = 0; ii < 16; ii++) {
            float4 xv = *(const float4*)(&Xsm[ii * NB + b0]);   // 2 complex
#pragma unroll
            for (int j = 0; j < 8; j++) {
                float2 kv = Ksm[(og + 16 * j) * 16 + ii];
                acc[j][0].x += kv.x * xv.x - kv.y * xv.y;
                acc[j][0].y += kv.x * xv.y + kv.y * xv.x;
                acc[j][1].x += kv.x * xv.z - kv.y * xv.w;
                acc[j][1].y += kv.x * xv.w + kv.y * xv.z;
            }
        }
        __syncthreads();
    }

    float2* Yf = g_Yf + (size_t)f * OB;
#pragma unroll
    for (int j = 0; j < 8; j++) {
        int o = og + 16 * j;
        float4 st = make_float4(acc[j][0].x, acc[j][0].y, acc[j][1].x, acc[j][1].y);
        *(float4*)(&Yf[o * NB + b0]) = st;
    }
}

// ------- 4) inverse over u: Z[h,v,ob] = sum_u conjF[h,u] * Yf[u,v,ob] --------
__global__ void k_ifft_u() {
    extern __shared__ char smem[];
    float2* Fc  = (float2*)smem;      // conj(F), 3136
    float2* Ysm = Fc + HW;            // [56(u)][64]
    int v   = blockIdx.y;             // 0..28
    int obt = blockIdx.x;             // 64 tiles of 64
    int tid = threadIdx.x;
    int hg  = tid >> 6;               // 4 h-groups of 14
    int obl = tid & 63;

    for (int t = tid; t < HW; t += 256) {
        float2 f = g_F[t];
        Fc[t] = make_float2(f.x, -f.y);
    }
    for (int t = tid; t < NN * 64; t += 256) {
        int uu = t >> 6, oo = t & 63;
        Ysm[t] = g_Yf[(size_t)(uu * NV + v) * OB + obt * 64 + oo];
    }
    __syncthreads();

    float2 acc[14];
#pragma unroll
    for (int hi = 0; hi < 14; hi++) acc[hi] = make_float2(0.f, 0.f);

#pragma unroll 4
    for (int u = 0; u < NN; u++) {
        float2 y = Ysm[u * 64 + obl];
#pragma unroll
        for (int hi = 0; hi < 14; hi++) {
            float2 fc = Fc[(hg * 14 + hi) * NN + u];
            acc[hi].x += fc.x * y.x - fc.y * y.y;
            acc[hi].y += fc.x * y.y + fc.y * y.x;
        }
    }
    int ob = obt * 64 + obl;
#pragma unroll
    for (int hi = 0; hi < 14; hi++)
        g_Z[(size_t)((hg * 14 + hi) * NV + v) * OB + ob] = acc[hi];
}

// ------- 5) Hermitian inverse over v (real output), scale 1/N^2 --------------
// y[h,w] = (Z0 + (-1)^w Z28 + 2*sum_{v=1..27} Re(Z[v] e^{+2pi i v w/56})) / 3136
// e^{+i t} with F = e^{-i t}:  Re(Z e^{+it}) = Zr*F.x + Zi*F.y
__global__ void k_ifft_v() {
    extern __shared__ char smem[];
    float2* Fs  = (float2*)smem;      // F, 3136
    float2* Zsm = Fs + HW;            // [29(v)][64]
    int h   = blockIdx.y;             // 0..55
    int obt = blockIdx.x;
    int tid = threadIdx.x;
    int wg  = tid >> 6;               // 4 w-groups of 14
    int obl = tid & 63;

    for (int t = tid; t < HW; t += 256) Fs[t] = g_F[t];
    for (int t = tid; t < NV * 64; t += 256) {
        int v = t >> 6, oo = t & 63;
        Zsm[t] = g_Z[(size_t)(h * NV + v) * OB + obt * 64 + oo];
    }
    __syncthreads();

    float acc[14];
#pragma unroll
    for (int wi = 0; wi < 14; wi++) acc[wi] = 0.f;

#pragma unroll 4
    for (int v = 1; v < 28; v++) {
        float2 z = Zsm[v * 64 + obl];
#pragma unroll
        for (int wi = 0; wi < 14; wi++) {
            float2 f = Fs[(wg * 14 + wi) * NN + v];
            acc[wi] += z.x * f.x + z.y * f.y;
        }
    }
    float z0  = Zsm[0 * 64 + obl].x;
    float z28 = Zsm[28 * 64 + obl].x;
    const float s = 1.0f / (float)HW;
    int ob = obt * 64 + obl;
#pragma unroll
    for (int wi = 0; wi < 14; wi++) {
        int w = wg * 14 + wi;
        float par = (w & 1) ? -z28 : z28;
        g_Y2[(size_t)(h * NN + w) * OB + ob] = (z0 + par + 2.0f * acc[wi]) * s;
    }
}

// ------- 6) final transpose [hw][ob] -> [b][o][hw] + bias --------------------
__global__ void k_out(const float* __restrict__ bias, float* __restrict__ out) {
    __shared__ float tile[32][33];
    int hw0 = blockIdx.x * 32;
    int ob0 = blockIdx.y * 32;
    int tx = threadIdx.x, ty = threadIdx.y;
#pragma unroll
    for (int k = 0; k < 4; k++)
        tile[ty + k * 8][tx] = g_Y2[(size_t)(hw0 + ty + k * 8) * OB + ob0 + tx];
    __syncthreads();
#pragma unroll
    for (int k = 0; k < 4; k++) {
        int ob = ob0 + ty + k * 8;
        int o = ob >> 5, b = ob & 31;       // ob = o*32 + b
        out[(size_t)(b * CO + o) * HW + hw0 + tx] = tile[tx][ty + k * 8] + bias[o];
    }
}

// ---------------- launch -----------------------------------------------------
extern "C" void kernel_launch(void* const* d_in, const int* in_sizes, int n_in,
                              void* d_out, int out_size) {
    const float* x    = (const float*)d_in[0];   // [32,64,56,56]
    const float* kr   = (const float*)d_in[1];   // [128,64,56,56]
    const float* ki   = (const float*)d_in[2];   // [128,64,56,56]
    const float* bias = (const float*)d_in[3];   // [128]
    float* out = (float*)d_out;                  // [32,128,56,56]

    const int smem_fwd = HW * (int)sizeof(float) + (HW + NN * 30) * (int)sizeof(float2); // 51072
    const int smem_iu  = (HW + NN * 64) * (int)sizeof(float2);                            // 53760
    const int smem_iv  = (HW + NV * 64) * (int)sizeof(float2);                            // 39936
    cudaFuncSetAttribute(k_fwd_fft, cudaFuncAttributeMaxDynamicSharedMemorySize, smem_fwd);
    cudaFuncSetAttribute(k_ifft_u, cudaFuncAttributeMaxDynamicSharedMemorySize, smem_iu);
    cudaFuncSetAttribute(k_ifft_v, cudaFuncAttributeMaxDynamicSharedMemorySize, smem_iv);

    k_init_F<<<(HW + 255) / 256, 256>>>();
    k_transpose_K<<<dim3((NF + 31) / 32, OI / 32), dim3(32, 8)>>>(kr, ki);
    k_fwd_fft<<<IB, 256, smem_fwd>>>(x);
    k_einsum<<<NF, 256>>>();
    k_ifft_u<<<dim3(64, NV), 256, smem_iu>>>();
    k_ifft_v<<<dim3(64, NN), 256, smem_iv>>>();
    k_out<<<dim3(HW / 32, OB / 32), dim3(32, 8)>>>(bias, out);
}

// round 4
// speedup vs baseline: 2.1060x; 1.2830x over previous
#include <cuda_runtime.h>
#include <math_constants.h>

// Problem constants
#define NN 56
#define HW 3136          // 56*56
#define NV 29            // rfft columns: v in [0,28]
#define NF (NN*NV)       // 1624 retained frequencies
#define NB 32            // batch
#define CI 64
#define CO 128
#define OB 4096          // CO*NB
#define IB 2048          // CI*NB
#define OI 8192          // CO*CI

// ---------------- scratch (device globals; no runtime allocation allowed) ----
__device__ __align__(16) float2 g_F [HW];                  // F[j*56+k] = e^{-2pi i jk/56}
__device__ __align__(16) float2 g_Kt[(size_t)NF * OI];     // [u*29+v][o*64+i]   106 MB
__device__ __align__(16) float2 g_Xf[(size_t)NF * IB];     // [u*29+v][i*32+b]    27 MB
__device__ __align__(16) float2 g_Yf[(size_t)NF * OB];     // [u*29+v][o*32+b]    53 MB
__device__ __align__(16) float2 g_Z [(size_t)NF * OB];     // [h*29+v][o*32+b]    53 MB

// ---------------- 0) twiddle init -------------------------------------------
__global__ void k_init_F() {
    int idx = blockIdx.x * blockDim.x + threadIdx.x;
    if (idx < HW) {
        int j = idx / NN, k = idx % NN;
        int m = (j * k) % NN;                       // exact angle reduction
        float ang = -2.0f * CUDART_PI_F * (float)m / (float)NN;
        float s, c;
        sincosf(ang, &s, &c);
        g_F[idx] = make_float2(c, s);
    }
}

// ------- 1) kernel transpose: [oi][f=u*56+v, v<29] -> float2 [u*29+v][oi] ----
__global__ void k_transpose_K(const float* __restrict__ kr, const float* __restrict__ ki) {
    __shared__ float2 tile[32][33];
    int fi0 = blockIdx.x * 32;            // fidx tile (fidx = u*29+v)
    int oi0 = blockIdx.y * 32;
    int tx = threadIdx.x, ty = threadIdx.y;
    int fi = fi0 + tx;
    int valid = fi < NF;
    int u = fi / NV, v = fi - u * NV;
    int fsrc = u * NN + v;                // source column in full spectrum
#pragma unroll
    for (int k = 0; k < 4; k++) {
        int oi = oi0 + ty + k * 8;
        if (valid) {
            size_t src = (size_t)oi * HW + fsrc;
            tile[ty + k * 8][tx] = make_float2(kr[src], ki[src]);
        }
    }
    __syncthreads();
#pragma unroll
    for (int k = 0; k < 4; k++) {
        int f = fi0 + ty + k * 8;
        if (f < NF)
            g_Kt[(size_t)f * OI + oi0 + tx] = tile[tx][ty + k * 8];
    }
}

// ------- 2) forward rfft2 per (b,i), register-blocked (7 rows per thread) ----
__global__ void k_fwd_fft(const float* __restrict__ x) {
    extern __shared__ char smem[];
    float*  xs = (float*)smem;                         // [3136]
    float2* Fs = (float2*)(smem + HW * sizeof(float)); // [3136]
    float2* A1 = Fs + HW;                              // [56][30]+pad

    int bi = blockIdx.x;                 // b*64 + i
    int b  = bi / CI, ci = bi % CI;
    int tid = threadIdx.x;

    for (int t = tid; t < HW; t += 256) {
        Fs[t] = g_F[t];
        xs[t] = x[(size_t)bi * HW + t];
    }
    __syncthreads();

    int lane = tid & 31;   // v (active when lane < 29)
    int grp  = tid >> 5;   // 0..7 -> 7 rows each

    // stage a: A1[h,v] = sum_w x[h,w] * F[w,v]; thread: h = grp*7+j, v = lane
    {
        float ar[7], ai[7];
#pragma unroll
        for (int j = 0; j < 7; j++) { ar[j] = 0.f; ai[j] = 0.f; }
        for (int w = 0; w < NN; w++) {
            float2 fv = Fs[w * NN + lane];           // conflict-free
#pragma unroll
            for (int j = 0; j < 7; j++) {
                float xv = xs[(grp * 7 + j) * NN + w];  // broadcast in warp
                ar[j] += xv * fv.x;
                ai[j] += xv * fv.y;
            }
        }
        if (lane < NV) {
#pragma unroll
            for (int j = 0; j < 7; j++)
                A1[(grp * 7 + j) * 30 + lane] = make_float2(ar[j], ai[j]);
        }
    }
    __syncthreads();

    // stage b: Xf[u,v] = sum_h F[u,h] * A1[h,v]; thread: u = grp*7+j, v = lane
    {
        float cr[7], cim[7];
#pragma unroll
        for (int j = 0; j < 7; j++) { cr[j] = 0.f; cim[j] = 0.f; }
        for (int h = 0; h < NN; h++) {
            float2 av = A1[h * 30 + lane];           // safe: A1 padded
#pragma unroll
            for (int j = 0; j < 7; j++) {
                float2 fv = Fs[(grp * 7 + j) * NN + h];  // broadcast in warp
                cr[j]  += fv.x * av.x - fv.y * av.y;
                cim[j] += fv.x * av.y + fv.y * av.x;
            }
        }
        if (lane < NV) {
            int col = ci * NB + b;
#pragma unroll
            for (int j = 0; j < 7; j++)
                g_Xf[(size_t)((grp * 7 + j) * NV + lane) * IB + col] =
                    make_float2(cr[j], cim[j]);
        }
    }
}

// ------- 3) per-frequency complex GEMM: Yf[o,b] = sum_i K[o,i]X[i,b] ---------
__global__ void __launch_bounds__(256, 2) k_einsum() {
    __shared__ __align__(16) float2 Ksm[CO * 32];   // [o][ii]  32KB
    __shared__ __align__(16) float2 Xsm[32 * NB];   // [ii][b]   8KB
    int f   = blockIdx.x;                 // fidx
    int tid = threadIdx.x;
    int b0  = (tid & 15) * 2;     // 2 consecutive b per thread
    int og  = tid >> 4;           // o = og + 16*j, j=0..7

    float2 acc[8][2];
#pragma unroll
    for (int j = 0; j < 8; j++) {
        acc[j][0] = make_float2(0.f, 0.f);
        acc[j][1] = make_float2(0.f, 0.f);
    }

    const float2* Kf = g_Kt + (size_t)f * OI;
    const float2* Xf = g_Xf + (size_t)f * IB;

    for (int ic = 0; ic < 2; ic++) {              // i chunks of 32
#pragma unroll
        for (int t = tid; t < CO * 32; t += 256) {
            int o = t >> 5, ii = t & 31;
            Ksm[t] = Kf[o * CI + ic * 32 + ii];
        }
#pragma unroll
        for (int t = tid; t < 32 * NB; t += 256)
            Xsm[t] = Xf[ic * 1024 + t];
        __syncthreads();

#pragma unroll 4
        for (int ii = 0; ii < 32; ii++) {
            float4 xv = *(const float4*)(&Xsm[ii * NB + b0]);   // 2 complex
            float2 kv[8];
#pragma unroll
            for (int j = 0; j < 8; j++)
                kv[j] = Ksm[(og + 16 * j) * 32 + ii];
#pragma unroll
            for (int j = 0; j < 8; j++) {
                acc[j][0].x += kv[j].x * xv.x - kv[j].y * xv.y;
                acc[j][0].y += kv[j].x * xv.y + kv[j].y * xv.x;
                acc[j][1].x += kv[j].x * xv.z - kv[j].y * xv.w;
                acc[j][1].y += kv[j].x * xv.w + kv[j].y * xv.z;
            }
        }
        __syncthreads();
    }

    float2* Yf = g_Yf + (size_t)f * OB;
#pragma unroll
    for (int j = 0; j < 8; j++) {
        int o = og + 16 * j;
        float4 st = make_float4(acc[j][0].x, acc[j][0].y, acc[j][1].x, acc[j][1].y);
        *(float4*)(&Yf[o * NB + b0]) = st;
    }
}

// ------- 4) inverse over u: Z[h,v,ob] = sum_u conjF[h,u] * Yf[u,v,ob] --------
__global__ void k_ifft_u() {
    extern __shared__ char smem[];
    float2* Fc  = (float2*)smem;      // conj(F), 3136
    float2* Ysm = Fc + HW;            // [56(u)][64]
    int v   = blockIdx.y;             // 0..28
    int obt = blockIdx.x;             // 64 tiles of 64
    int tid = threadIdx.x;
    int hg  = tid >> 6;               // 4 h-groups of 14
    int obl = tid & 63;

    for (int t = tid; t < HW; t += 256) {
        float2 f = g_F[t];
        Fc[t] = make_float2(f.x, -f.y);
    }
    for (int t = tid; t < NN * 64; t += 256) {
        int uu = t >> 6, oo = t & 63;
        Ysm[t] = g_Yf[(size_t)(uu * NV + v) * OB + obt * 64 + oo];
    }
    __syncthreads();

    float2 acc[14];
#pragma unroll
    for (int hi = 0; hi < 14; hi++) acc[hi] = make_float2(0.f, 0.f);

#pragma unroll 4
    for (int u = 0; u < NN; u++) {
        float2 y = Ysm[u * 64 + obl];
#pragma unroll
        for (int hi = 0; hi < 14; hi++) {
            float2 fc = Fc[(hg * 14 + hi) * NN + u];
            acc[hi].x += fc.x * y.x - fc.y * y.y;
            acc[hi].y += fc.x * y.y + fc.y * y.x;
        }
    }
    int ob = obt * 64 + obl;
#pragma unroll
    for (int hi = 0; hi < 14; hi++)
        g_Z[(size_t)((hg * 14 + hi) * NV + v) * OB + ob] = acc[hi];
}

// ------- 5) Hermitian inverse over v + bias + final layout, fused ------------
// y[h,w] = (Z0 + (-1)^w Z28 + 2*sum_{v=1..27} Re(Z[v] e^{+2pi i v w/56})) / 3136
// Re(Z e^{+it}) with F = e^{-it}:  Zr*F.x + Zi*F.y
__global__ void k_ifft_v_out(const float* __restrict__ bias, float* __restrict__ out) {
    extern __shared__ char smem[];
    float2* FsC = (float2*)smem;               // [56][28] compact twiddles
    float2* Zsm = FsC + NN * 28;               // [29][64]
    float*  Ysm = (float*)(Zsm + NV * 64);     // [56][65] (padded)
    int h   = blockIdx.y;             // 0..55
    int obt = blockIdx.x;             // 64 tiles of 64
    int tid = threadIdx.x;
    int wg  = tid >> 6;               // 4 w-groups of 14
    int obl = tid & 63;

    for (int t = tid; t < NN * 28; t += 256) {
        int w = t / 28, v = t - w * 28;
        FsC[t] = g_F[w * NN + v];
    }
    for (int t = tid; t < NV * 64; t += 256) {
        int v = t >> 6, oo = t & 63;
        Zsm[t] = g_Z[(size_t)(h * NV + v) * OB + obt * 64 + oo];
    }
    __syncthreads();

    float acc[14];
#pragma unroll
    for (int wi = 0; wi < 14; wi++) acc[wi] = 0.f;

#pragma unroll 4
    for (int v = 1; v < 28; v++) {
        float2 z = Zsm[v * 64 + obl];
#pragma unroll
        for (int wi = 0; wi < 14; wi++) {
            float2 f = FsC[(wg * 14 + wi) * 28 + v];
            acc[wi] += z.x * f.x + z.y * f.y;
        }
    }
    float z0  = Zsm[obl].x;
    float z28 = Zsm[28 * 64 + obl].x;
    const float s = 1.0f / (float)HW;
#pragma unroll
    for (int wi = 0; wi < 14; wi++) {
        int w = wg * 14 + wi;
        float par = (w & 1) ? -z28 : z28;
        Ysm[w * 65 + obl] = (z0 + par + 2.0f * acc[wi]) * s;
    }
    __syncthreads();

    // coalesced-ish final write: consecutive threads -> consecutive w
    for (int t = tid; t < NN * 64; t += 256) {
        int lob = t / NN, w = t - lob * NN;
        int ob = obt * 64 + lob;
        int o = ob >> 5, bb = ob & 31;       // ob = o*32 + b
        out[(size_t)(bb * CO + o) * HW + h * NN + w] = Ysm[w * 65 + lob] + bias[o];
    }
}

// ---------------- launch -----------------------------------------------------
extern "C" void kernel_launch(void* const* d_in, const int* in_sizes, int n_in,
                              void* d_out, int out_size) {
    const float* x    = (const float*)d_in[0];   // [32,64,56,56]
    const float* kr   = (const float*)d_in[1];   // [128,64,56,56]
    const float* ki   = (const float*)d_in[2];   // [128,64,56,56]
    const float* bias = (const float*)d_in[3];   // [128]
    float* out = (float*)d_out;                  // [32,128,56,56]

    const int smem_fwd = HW * (int)sizeof(float) + (HW + NN * 30 + 8) * (int)sizeof(float2);
    const int smem_iu  = (HW + NN * 64) * (int)sizeof(float2);
    const int smem_iv  = (NN * 28 + NV * 64) * (int)sizeof(float2) + NN * 65 * (int)sizeof(float);
    cudaFuncSetAttribute(k_fwd_fft, cudaFuncAttributeMaxDynamicSharedMemorySize, smem_fwd);
    cudaFuncSetAttribute(k_ifft_u, cudaFuncAttributeMaxDynamicSharedMemorySize, smem_iu);
    cudaFuncSetAttribute(k_ifft_v_out, cudaFuncAttributeMaxDynamicSharedMemorySize, smem_iv);

    k_init_F<<<(HW + 255) / 256, 256>>>();
    k_transpose_K<<<dim3((NF + 31) / 32, OI / 32), dim3(32, 8)>>>(kr, ki);
    k_fwd_fft<<<IB, 256, smem_fwd>>>(x);
    k_einsum<<<NF, 256>>>();
    k_ifft_u<<<dim3(64, NV), 256, smem_iu>>>();
    k_ifft_v_out<<<dim3(64, NN), 256, smem_iv>>>(bias, out);
}

// round 5
// speedup vs baseline: 2.2542x; 1.0704x over previous
#include <cuda_runtime.h>
#include <math_constants.h>

// Problem constants
#define NN 56
#define HW 3136          // 56*56
#define NV 29            // rfft columns: v in [0,28]
#define NF (NN*NV)       // 1624 retained frequencies
#define NB 32            // batch
#define CI 64
#define CO 128
#define OB 4096          // CO*NB
#define IB 2048          // CI*NB
#define OI 8192          // CO*CI

// ---------------- scratch (device globals; no runtime allocation allowed) ----
__device__ __align__(16) float2 g_F [HW];                  // F[j*56+k] = e^{-2pi i jk/56}
__device__ __align__(16) float2 g_Kt[(size_t)NF * OI];     // [u*29+v][o*64+i]   106 MB
__device__ __align__(16) float2 g_Xf[(size_t)NF * IB];     // [u*29+v][i*32+b]    27 MB
__device__ __align__(16) float2 g_Yf[(size_t)NF * OB];     // [u*29+v][o*32+b]    53 MB
__device__ __align__(16) float2 g_Z [(size_t)NF * OB];     // [h*29+v][o*32+b]    53 MB

// ---------------- 0) twiddle init -------------------------------------------
__global__ void k_init_F() {
    int idx = blockIdx.x * blockDim.x + threadIdx.x;
    if (idx < HW) {
        int j = idx / NN, k = idx % NN;
        int m = (j * k) % NN;                       // exact angle reduction
        float ang = -2.0f * CUDART_PI_F * (float)m / (float)NN;
        float s, c;
        sincosf(ang, &s, &c);
        g_F[idx] = make_float2(c, s);
    }
}

// ------- 1) kernel transpose: [oi][f=u*56+v, v<29] -> float2 [u*29+v][oi] ----
__global__ void k_transpose_K(const float* __restrict__ kr, const float* __restrict__ ki) {
    __shared__ float2 tile[32][33];
    int fi0 = blockIdx.x * 32;            // fidx tile (fidx = u*29+v)
    int oi0 = blockIdx.y * 32;
    int tx = threadIdx.x, ty = threadIdx.y;
    int fi = fi0 + tx;
    int valid = fi < NF;
    int u = fi / NV, v = fi - u * NV;
    int fsrc = u * NN + v;                // source column in full spectrum
#pragma unroll
    for (int k = 0; k < 4; k++) {
        int oi = oi0 + ty + k * 8;
        if (valid) {
            size_t src = (size_t)oi * HW + fsrc;
            tile[ty + k * 8][tx] = make_float2(kr[src], ki[src]);
        }
    }
    __syncthreads();
#pragma unroll
    for (int k = 0; k < 4; k++) {
        int f = fi0 + ty + k * 8;
        if (f < NF)
            g_Kt[(size_t)f * OI + oi0 + tx] = tile[tx][ty + k * 8];
    }
}

// ------- 2) forward rfft2 per (b,i), conjugate-pair factorized ---------------
__global__ void k_fwd_fft(const float* __restrict__ x) {
    extern __shared__ char smem[];
    float*  xs  = (float*)smem;                            // [3136]
    float2* Fs  = (float2*)(smem + HW * sizeof(float));    // [29][56] rows j<=28
    float2* A1  = Fs + 29 * NN;                            // [56][30]
    float2* sdm = A1 + NN * 30;                            // [56][28]: w=0 slot holds (x0,x28)

    int bi = blockIdx.x;                 // b*64 + i
    int b  = bi / CI, ci = bi % CI;
    int tid = threadIdx.x;

    for (int t = tid; t < 29 * NN; t += 256) Fs[t] = g_F[t];   // first 29 rows contiguous
    for (int t = tid; t < HW; t += 256) xs[t] = x[(size_t)bi * HW + t];
    __syncthreads();

    // build sum/diff table: sdm[h][w] = (x[h][w]+x[h][56-w], x[h][w]-x[h][56-w]) for w=1..27
    //                       sdm[h][0] = (x[h][0], x[h][28])
    for (int t = tid; t < NN * 28; t += 256) {
        int h = t / 28, w = t - h * 28;
        const float* xr = xs + h * NN;
        sdm[t] = (w == 0) ? make_float2(xr[0], xr[28])
                          : make_float2(xr[w] + xr[NN - w], xr[w] - xr[NN - w]);
    }
    __syncthreads();

    int lane = tid & 31;   // v (active when lane < 29)
    int grp  = tid >> 5;   // 0..7

    // stage a: A1[h,v] = x0 + (-1)^v x28 + sum_{w=1..27} (F.x*s + i F.y*d)
    {
        float ar[7], ai[7];
        float sgn = (lane & 1) ? -1.f : 1.f;
#pragma unroll
        for (int j = 0; j < 7; j++) {
            float2 sd0 = sdm[(grp * 7 + j) * 28];
            ar[j] = sd0.x + sgn * sd0.y;
            ai[j] = 0.f;
        }
        for (int w = 1; w < 28; w++) {
            float2 fv = Fs[w * NN + lane];
#pragma unroll
            for (int j = 0; j < 7; j++) {
                float2 sd = sdm[(grp * 7 + j) * 28 + w];   // broadcast in warp
                ar[j] += fv.x * sd.x;
                ai[j] += fv.y * sd.y;
            }
        }
        if (lane < NV) {
#pragma unroll
            for (int j = 0; j < 7; j++)
                A1[(grp * 7 + j) * 30 + lane] = make_float2(ar[j], ai[j]);
        }
    }
    __syncthreads();

    // stage b: pairs u=p and 56-p via separated sums.
    // thread: v=lane, pairs p = grp + 8*j (j=0..3), valid p<=28
    {
        float Sap[4], Sbq[4], Saq[4], Sbp[4];
#pragma unroll
        for (int j = 0; j < 4; j++) { Sap[j] = Sbq[j] = Saq[j] = Sbp[j] = 0.f; }
        for (int h = 0; h < NN; h++) {
            float2 av = A1[h * 30 + lane];
#pragma unroll
            for (int j = 0; j < 4; j++) {
                int p = grp + 8 * j;                       // <=31; rows 29..31 wasted
                float2 fv = Fs[(p & 31) * NN + h];         // p<=31 but Fs has 29 rows; mask safe? no!
                Sap[j] += fv.x * av.x;
                Sbq[j] += fv.y * av.y;
                Saq[j] += fv.x * av.y;
                Sbp[j] += fv.y * av.x;
            }
        }
        if (lane < NV) {
            int col = ci * NB + b;
#pragma unroll
            for (int j = 0; j < 4; j++) {
                int p = grp + 8 * j;
                if (p <= 28) {
                    g_Xf[(size_t)(p * NV + lane) * IB + col] =
                        make_float2(Sap[j] - Sbq[j], Saq[j] + Sbp[j]);
                    if (p != 0 && p != 28)
                        g_Xf[(size_t)((NN - p) * NV + lane) * IB + col] =
                            make_float2(Sap[j] + Sbq[j], Saq[j] - Sbp[j]);
                }
            }
        }
    }
}

// ------- 3) per-frequency complex GEMM: Yf[o,b] = sum_i K[o,i]X[i,b] ---------
__global__ void __launch_bounds__(256, 2) k_einsum() {
    __shared__ __align__(16) float2 Ksm[CO * 32];   // [o][ii]  32KB
    __shared__ __align__(16) float2 Xsm[32 * NB];   // [ii][b]   8KB
    int f   = blockIdx.x;                 // fidx
    int tid = threadIdx.x;
    int b0  = (tid & 15) * 2;     // 2 consecutive b per thread
    int og  = tid >> 4;           // o = og + 16*j, j=0..7

    float2 acc[8][2];
#pragma unroll
    for (int j = 0; j < 8; j++) {
        acc[j][0] = make_float2(0.f, 0.f);
        acc[j][1] = make_float2(0.f, 0.f);
    }

    const float2* Kf = g_Kt + (size_t)f * OI;
    const float2* Xf = g_Xf + (size_t)f * IB;

    for (int ic = 0; ic < 2; ic++) {              // i chunks of 32
#pragma unroll
        for (int t = tid; t < CO * 32; t += 256) {
            int o = t >> 5, ii = t & 31;
            Ksm[t] = Kf[o * CI + ic * 32 + ii];
        }
#pragma unroll
        for (int t = tid; t < 32 * NB; t += 256)
            Xsm[t] = Xf[ic * 1024 + t];
        __syncthreads();

#pragma unroll 4
        for (int ii = 0; ii < 32; ii++) {
            float4 xv = *(const float4*)(&Xsm[ii * NB + b0]);   // 2 complex
            float2 kv[8];
#pragma unroll
            for (int j = 0; j < 8; j++)
                kv[j] = Ksm[(og + 16 * j) * 32 + ii];
#pragma unroll
            for (int j = 0; j < 8; j++) {
                acc[j][0].x += kv[j].x * xv.x - kv[j].y * xv.y;
                acc[j][0].y += kv[j].x * xv.y + kv[j].y * xv.x;
                acc[j][1].x += kv[j].x * xv.z - kv[j].y * xv.w;
                acc[j][1].y += kv[j].x * xv.w + kv[j].y * xv.z;
            }
        }
        __syncthreads();
    }

    float2* Yf = g_Yf + (size_t)f * OB;
#pragma unroll
    for (int j = 0; j < 8; j++) {
        int o = og + 16 * j;
        float4 st = make_float4(acc[j][0].x, acc[j][0].y, acc[j][1].x, acc[j][1].y);
        *(float4*)(&Yf[o * NB + b0]) = st;
    }
}

// ------- 4) inverse over u, conjugate-pair factorized ------------------------
// Z[h,v] = Y0 + (-1)^h Y28 + sum_{u=1..27} [a*P.x - b*M.y + i(a*P.y + b*M.x)]
// (a,b) = conjF[h,u] = (F.x, -F.y); P = Y[u]+Y[56-u], M = Y[u]-Y[56-u]
__global__ void k_ifft_u() {
    extern __shared__ char smem[];
    float2* Fc  = (float2*)smem;      // [56][27] compact: (cos, +sin)
    float2* Ysm = Fc + NN * 27;       // [56(u)][64]
    int v   = blockIdx.y;             // 0..28
    int obt = blockIdx.x;             // 64 tiles of 64
    int tid = threadIdx.x;
    int hg  = tid >> 6;               // 4 h-groups of 14
    int obl = tid & 63;

    for (int t = tid; t < NN * 27; t += 256) {
        int h = t / 27, u = t - h * 27 + 1;
        float2 f = g_F[h * NN + u];
        Fc[t] = make_float2(f.x, -f.y);
    }
    for (int t = tid; t < NN * 64; t += 256) {
        int uu = t >> 6, oo = t & 63;
        Ysm[t] = g_Yf[(size_t)(uu * NV + v) * OB + obt * 64 + oo];
    }
    __syncthreads();

    float2 Y0  = Ysm[obl];
    float2 Y28 = Ysm[28 * 64 + obl];
    float2 acc[14];
#pragma unroll
    for (int hi = 0; hi < 14; hi++) {
        int h = hg * 14 + hi;
        float sg = (h & 1) ? -1.f : 1.f;
        acc[hi] = make_float2(Y0.x + sg * Y28.x, Y0.y + sg * Y28.y);
    }

#pragma unroll 3
    for (int up = 1; up < 28; up++) {
        float2 Yu = Ysm[up * 64 + obl];
        float2 Ym = Ysm[(NN - up) * 64 + obl];
        float2 P = make_float2(Yu.x + Ym.x, Yu.y + Ym.y);
        float2 M = make_float2(Yu.x - Ym.x, Yu.y - Ym.y);
#pragma unroll
        for (int hi = 0; hi < 14; hi++) {
            float2 c = Fc[(hg * 14 + hi) * 27 + up - 1];
            acc[hi].x += c.x * P.x - c.y * M.y;
            acc[hi].y += c.x * P.y + c.y * M.x;
        }
    }
    int ob = obt * 64 + obl;
#pragma unroll
    for (int hi = 0; hi < 14; hi++)
        g_Z[(size_t)((hg * 14 + hi) * NV + v) * OB + ob] = acc[hi];
}

// ------- 5) Hermitian inverse over v + bias + final layout, fused ------------
__global__ void k_ifft_v_out(const float* __restrict__ bias, float* __restrict__ out) {
    extern __shared__ char smem[];
    float2* FsC = (float2*)smem;               // [56][28] compact twiddles
    float2* Zsm = FsC + NN * 28;               // [29][64]
    float*  Ysm = (float*)(Zsm + NV * 64);     // [56][65] (padded)
    int h   = blockIdx.y;             // 0..55
    int obt = blockIdx.x;             // 64 tiles of 64
    int tid = threadIdx.x;
    int wg  = tid >> 6;               // 4 w-groups of 14
    int obl = tid & 63;

    for (int t = tid; t < NN * 28; t += 256) {
        int w = t / 28, v = t - w * 28;
        FsC[t] = g_F[w * NN + v];
    }
    for (int t = tid; t < NV * 64; t += 256) {
        int v = t >> 6, oo = t & 63;
        Zsm[t] = g_Z[(size_t)(h * NV + v) * OB + obt * 64 + oo];
    }
    __syncthreads();

    float acc[14];
#pragma unroll
    for (int wi = 0; wi < 14; wi++) acc[wi] = 0.f;

#pragma unroll 4
    for (int v = 1; v < 28; v++) {
        float2 z = Zsm[v * 64 + obl];
#pragma unroll
        for (int wi = 0; wi < 14; wi++) {
            float2 f = FsC[(wg * 14 + wi) * 28 + v];
            acc[wi] += z.x * f.x + z.y * f.y;
        }
    }
    float z0  = Zsm[obl].x;
    float z28 = Zsm[28 * 64 + obl].x;
    const float s = 1.0f / (float)HW;
#pragma unroll
    for (int wi = 0; wi < 14; wi++) {
        int w = wg * 14 + wi;
        float par = (w & 1) ? -z28 : z28;
        Ysm[w * 65 + obl] = (z0 + par + 2.0f * acc[wi]) * s;
    }
    __syncthreads();

    for (int t = tid; t < NN * 64; t += 256) {
        int lob = t / NN, w = t - lob * NN;
        int ob = obt * 64 + lob;
        int o = ob >> 5, bb = ob & 31;       // ob = o*32 + b
        out[(size_t)(bb * CO + o) * HW + h * NN + w] = Ysm[w * 65 + lob] + bias[o];
    }
}

// ---------------- launch -----------------------------------------------------
extern "C" void kernel_launch(void* const* d_in, const int* in_sizes, int n_in,
                              void* d_out, int out_size) {
    const float* x    = (const float*)d_in[0];   // [32,64,56,56]
    const float* kr   = (const float*)d_in[1];   // [128,64,56,56]
    const float* ki   = (const float*)d_in[2];   // [128,64,56,56]
    const float* bias = (const float*)d_in[3];   // [128]
    float* out = (float*)d_out;                  // [32,128,56,56]

    const int smem_fwd = HW * (int)sizeof(float)
                       + (29 * NN + NN * 30 + NN * 28) * (int)sizeof(float2);   // ~51.5KB
    const int smem_iu  = (NN * 27 + NN * 64) * (int)sizeof(float2);             // ~40.8KB
    const int smem_iv  = (NN * 28 + NV * 64) * (int)sizeof(float2) + NN * 65 * (int)sizeof(float);
    cudaFuncSetAttribute(k_fwd_fft, cudaFuncAttributeMaxDynamicSharedMemorySize, smem_fwd);
    cudaFuncSetAttribute(k_ifft_u, cudaFuncAttributeMaxDynamicSharedMemorySize, smem_iu);
    cudaFuncSetAttribute(k_ifft_v_out, cudaFuncAttributeMaxDynamicSharedMemorySize, smem_iv);

    k_init_F<<<(HW + 255) / 256, 256>>>();
    k_transpose_K<<<dim3((NF + 31) / 32, OI / 32), dim3(32, 8)>>>(kr, ki);
    k_fwd_fft<<<IB, 256, smem_fwd>>>(x);
    k_einsum<<<NF, 256>>>();
    k_ifft_u<<<dim3(64, NV), 256, smem_iu>>>();
    k_ifft_v_out<<<dim3(64, NN), 256, smem_iv>>>(bias, out);
}

// round 6
// speedup vs baseline: 2.6682x; 1.1836x over previous
#include <cuda_runtime.h>
#include <math_constants.h>

// Problem constants
#define NN 56
#define HW 3136          // 56*56
#define NV 29            // rfft columns: v in [0,28]
#define NF (NN*NV)       // 1624 retained frequencies
#define NB 32            // batch
#define CI 64
#define CO 128
#define OB 4096          // CO*NB
#define IB 2048          // CI*NB
#define OI 8192          // CO*CI

// ---------------- scratch (device globals; no runtime allocation allowed) ----
__device__ __align__(16) float2 g_F [HW];                  // F[j*56+k] = e^{-2pi i jk/56}
__device__ __align__(16) float2 g_Kt[(size_t)NF * OI];     // [u*29+v][o*64+i]   106 MB
__device__ __align__(16) float2 g_Xf[(size_t)NF * IB];     // [u*29+v][i*32+b]    27 MB
__device__ __align__(16) float2 g_Yf[(size_t)NF * OB];     // [u*29+v][o*32+b]    53 MB
__device__ __align__(16) float2 g_Z [(size_t)NF * OB];     // [h*29+v][o*32+b]    53 MB

// ---------------- 0) twiddle init -------------------------------------------
__global__ void k_init_F() {
    int idx = blockIdx.x * blockDim.x + threadIdx.x;
    if (idx < HW) {
        int j = idx / NN, k = idx % NN;
        int m = (j * k) % NN;                       // exact angle reduction
        float ang = -2.0f * CUDART_PI_F * (float)m / (float)NN;
        float s, c;
        sincosf(ang, &s, &c);
        g_F[idx] = make_float2(c, s);
    }
}

// ------- 1) kernel transpose: [oi][f=u*56+v, v<29] -> float2 [u*29+v][oi] ----
__global__ void k_transpose_K(const float* __restrict__ kr, const float* __restrict__ ki) {
    __shared__ float2 tile[32][33];
    int fi0 = blockIdx.x * 32;            // fidx tile (fidx = u*29+v)
    int oi0 = blockIdx.y * 32;
    int tx = threadIdx.x, ty = threadIdx.y;
    int fi = fi0 + tx;
    int valid = fi < NF;
    int u = fi / NV, v = fi - u * NV;
    int fsrc = u * NN + v;                // source column in full spectrum
#pragma unroll
    for (int k = 0; k < 4; k++) {
        int oi = oi0 + ty + k * 8;
        if (valid) {
            size_t src = (size_t)oi * HW + fsrc;
            tile[ty + k * 8][tx] = make_float2(kr[src], ki[src]);
        }
    }
    __syncthreads();
#pragma unroll
    for (int k = 0; k < 4; k++) {
        int f = fi0 + ty + k * 8;
        if (f < NF)
            g_Kt[(size_t)f * OI + oi0 + tx] = tile[tx][ty + k * 8];
    }
}

// ------- 2) forward rfft2 per (b,i), conjugate-pair factorized ---------------
__global__ void k_fwd_fft(const float* __restrict__ x) {
    extern __shared__ char smem[];
    float*  xs  = (float*)smem;                            // [3136]
    float2* Fs  = (float2*)(smem + HW * sizeof(float));    // [29][56] rows j<=28
    float2* A1  = Fs + 29 * NN;                            // [56][30]
    float2* sdm = A1 + NN * 30;                            // [56][28]

    int bi = blockIdx.x;                 // b*64 + i
    int b  = bi / CI, ci = bi % CI;
    int tid = threadIdx.x;

    for (int t = tid; t < 29 * NN; t += 256) Fs[t] = g_F[t];
    for (int t = tid; t < HW; t += 256) xs[t] = x[(size_t)bi * HW + t];
    __syncthreads();

    for (int t = tid; t < NN * 28; t += 256) {
        int h = t / 28, w = t - h * 28;
        const float* xr = xs + h * NN;
        sdm[t] = (w == 0) ? make_float2(xr[0], xr[28])
                          : make_float2(xr[w] + xr[NN - w], xr[w] - xr[NN - w]);
    }
    __syncthreads();

    int lane = tid & 31;   // v (active when lane < 29)
    int grp  = tid >> 5;   // 0..7

    // stage a
    {
        float ar[7], ai[7];
        float sgn = (lane & 1) ? -1.f : 1.f;
#pragma unroll
        for (int j = 0; j < 7; j++) {
            float2 sd0 = sdm[(grp * 7 + j) * 28];
            ar[j] = sd0.x + sgn * sd0.y;
            ai[j] = 0.f;
        }
        for (int w = 1; w < 28; w++) {
            float2 fv = Fs[w * NN + lane];
#pragma unroll
            for (int j = 0; j < 7; j++) {
                float2 sd = sdm[(grp * 7 + j) * 28 + w];
                ar[j] += fv.x * sd.x;
                ai[j] += fv.y * sd.y;
            }
        }
        if (lane < NV) {
#pragma unroll
            for (int j = 0; j < 7; j++)
                A1[(grp * 7 + j) * 30 + lane] = make_float2(ar[j], ai[j]);
        }
    }
    __syncthreads();

    // stage b: pair sums give Xf[p] and Xf[56-p]
    {
        float Sap[4], Sbq[4], Saq[4], Sbp[4];
#pragma unroll
        for (int j = 0; j < 4; j++) { Sap[j] = Sbq[j] = Saq[j] = Sbp[j] = 0.f; }
        for (int h = 0; h < NN; h++) {
            float2 av = A1[h * 30 + lane];
#pragma unroll
            for (int j = 0; j < 4; j++) {
                int p = grp + 8 * j;                 // <=31; rows>28 discarded
                float2 fv = Fs[(p & 31) * NN + h];   // in-bounds of dyn smem block
                Sap[j] += fv.x * av.x;
                Sbq[j] += fv.y * av.y;
                Saq[j] += fv.x * av.y;
                Sbp[j] += fv.y * av.x;
            }
        }
        if (lane < NV) {
            int col = ci * NB + b;
#pragma unroll
            for (int j = 0; j < 4; j++) {
                int p = grp + 8 * j;
                if (p <= 28) {
                    g_Xf[(size_t)(p * NV + lane) * IB + col] =
                        make_float2(Sap[j] - Sbq[j], Saq[j] + Sbp[j]);
                    if (p != 0 && p != 28)
                        g_Xf[(size_t)((NN - p) * NV + lane) * IB + col] =
                            make_float2(Sap[j] + Sbq[j], Saq[j] - Sbp[j]);
                }
            }
        }
    }
}

// ------- 3) per-frequency complex GEMM: Yf[o,b] = sum_i K[o,i]X[i,b] ---------
__global__ void __launch_bounds__(256, 2) k_einsum() {
    __shared__ __align__(16) float2 Ksm[CO * 32];   // [o][ii]  32KB
    __shared__ __align__(16) float2 Xsm[32 * NB];   // [ii][b]   8KB
    int f   = blockIdx.x;
    int tid = threadIdx.x;
    int b0  = (tid & 15) * 2;
    int og  = tid >> 4;

    float2 acc[8][2];
#pragma unroll
    for (int j = 0; j < 8; j++) {
        acc[j][0] = make_float2(0.f, 0.f);
        acc[j][1] = make_float2(0.f, 0.f);
    }

    const float2* Kf = g_Kt + (size_t)f * OI;
    const float2* Xf = g_Xf + (size_t)f * IB;

    for (int ic = 0; ic < 2; ic++) {
#pragma unroll
        for (int t = tid; t < CO * 32; t += 256) {
            int o = t >> 5, ii = t & 31;
            Ksm[t] = Kf[o * CI + ic * 32 + ii];
        }
#pragma unroll
        for (int t = tid; t < 32 * NB; t += 256)
            Xsm[t] = Xf[ic * 1024 + t];
        __syncthreads();

#pragma unroll 4
        for (int ii = 0; ii < 32; ii++) {
            float4 xv = *(const float4*)(&Xsm[ii * NB + b0]);
            float2 kv[8];
#pragma unroll
            for (int j = 0; j < 8; j++)
                kv[j] = Ksm[(og + 16 * j) * 32 + ii];
#pragma unroll
            for (int j = 0; j < 8; j++) {
                acc[j][0].x += kv[j].x * xv.x - kv[j].y * xv.y;
                acc[j][0].y += kv[j].x * xv.y + kv[j].y * xv.x;
                acc[j][1].x += kv[j].x * xv.z - kv[j].y * xv.w;
                acc[j][1].y += kv[j].x * xv.w + kv[j].y * xv.z;
            }
        }
        __syncthreads();
    }

    float2* Yf = g_Yf + (size_t)f * OB;
#pragma unroll
    for (int j = 0; j < 8; j++) {
        int o = og + 16 * j;
        float4 st = make_float4(acc[j][0].x, acc[j][0].y, acc[j][1].x, acc[j][1].y);
        *(float4*)(&Yf[o * NB + b0]) = st;
    }
}

// ------- 4) inverse over u, double conjugate-pair (u-pairs AND h-pairs) ------
// slot s<=26: h=s+1, also produces 56-h. slot 27: h=0 and h=28 (post-loop).
// S1=sum a*Px, S2=sum b*My, S3=sum a*Py, S4=sum b*Mx; (a,b)=(cos,sin)(2pi h u/56)
// Z[h]=(base.x+S1-S2, base.y+S3+S4); Z[56-h]=(base.x+S1+S2, base.y+S3-S4)
__global__ void k_ifft_u() {
    extern __shared__ char smem[];
    float2* Fc  = (float2*)smem;      // [28][27] rows: h=1..27 (cos,sin); row27 zero
    float2* Ysm = Fc + 28 * 27;       // [56(u)][64]
    int v   = blockIdx.y;             // 0..28
    int obt = blockIdx.x;
    int tid = threadIdx.x;
    int wg  = tid >> 6;               // 4 slot-groups of 7
    int obl = tid & 63;

    for (int t = tid; t < 28 * 27; t += 256) {
        int s = t / 27, u = t - s * 27 + 1;
        if (s < 27) {
            float2 f = g_F[(s + 1) * NN + u];
            Fc[t] = make_float2(f.x, -f.y);
        } else {
            Fc[t] = make_float2(0.f, 0.f);
        }
    }
    for (int t = tid; t < NN * 64; t += 256) {
        int uu = t >> 6, oo = t & 63;
        Ysm[t] = g_Yf[(size_t)(uu * NV + v) * OB + obt * 64 + oo];
    }
    __syncthreads();

    float2 Y0  = Ysm[obl];
    float2 Y28 = Ysm[28 * 64 + obl];

    float S1[7], S2[7], S3[7], S4[7];
#pragma unroll
    for (int j = 0; j < 7; j++) { S1[j] = S2[j] = S3[j] = S4[j] = 0.f; }

#pragma unroll 3
    for (int up = 1; up < 28; up++) {
        float2 Yu = Ysm[up * 64 + obl];
        float2 Ym = Ysm[(NN - up) * 64 + obl];
        float Px = Yu.x + Ym.x, Py = Yu.y + Ym.y;
        float Mx = Yu.x - Ym.x, My = Yu.y - Ym.y;
#pragma unroll
        for (int j = 0; j < 7; j++) {
            float2 c = Fc[(wg * 7 + j) * 27 + up - 1];
            S1[j] += c.x * Px;
            S2[j] += c.y * My;
            S3[j] += c.x * Py;
            S4[j] += c.y * Mx;
        }
    }

    int ob = obt * 64 + obl;
#pragma unroll
    for (int j = 0; j < 7; j++) {
        int s = wg * 7 + j;
        if (s < 27) {
            int h = s + 1;
            float sg = (h & 1) ? -1.f : 1.f;
            float bx = Y0.x + sg * Y28.x, by = Y0.y + sg * Y28.y;
            g_Z[(size_t)(h * NV + v) * OB + ob] =
                make_float2(bx + S1[j] - S2[j], by + S3[j] + S4[j]);
            g_Z[(size_t)((NN - h) * NV + v) * OB + ob] =
                make_float2(bx + S1[j] + S2[j], by + S3[j] - S4[j]);
        }
    }
    if (wg == 3) {   // slot 27: h=0 and h=28
        float2 a0 = make_float2(Y0.x + Y28.x, Y0.y + Y28.y);
        float2 a28 = a0;
        for (int up = 1; up < 28; up++) {
            float2 Yu = Ysm[up * 64 + obl];
            float2 Ym = Ysm[(NN - up) * 64 + obl];
            float Px = Yu.x + Ym.x, Py = Yu.y + Ym.y;
            float sg = (up & 1) ? -1.f : 1.f;
            a0.x += Px;        a0.y += Py;
            a28.x += sg * Px;  a28.y += sg * Py;
        }
        g_Z[(size_t)(0 * NV + v) * OB + ob]  = a0;
        g_Z[(size_t)(28 * NV + v) * OB + ob] = a28;
    }
}

// ------- 5) Hermitian inverse over v, w-paired, + bias + final layout --------
// slot s<=26: w=s+1 and 56-w; slot 27: w=0 and w=28.
// Sc=sum Zr*cos(2pi v w/56), Ss=sum Zi*sin; y[w]=base+2(Sc-Ss); y[56-w]=base+2(Sc+Ss)
__global__ void k_ifft_v_out(const float* __restrict__ bias, float* __restrict__ out) {
    extern __shared__ char smem[];
    float2* FsC = (float2*)smem;               // [28][27] (cos,sin); row27 zero
    float2* Zsm = FsC + 28 * 27;               // [29][64]
    float*  Ysm = (float*)(Zsm + NV * 64);     // [56][65]
    int h   = blockIdx.y;
    int obt = blockIdx.x;
    int tid = threadIdx.x;
    int wg  = tid >> 6;
    int obl = tid & 63;

    for (int t = tid; t < 28 * 27; t += 256) {
        int s = t / 27, v = t - s * 27 + 1;
        if (s < 27) {
            float2 f = g_F[(s + 1) * NN + v];
            FsC[t] = make_float2(f.x, -f.y);
        } else {
            FsC[t] = make_float2(0.f, 0.f);
        }
    }
    for (int t = tid; t < NV * 64; t += 256) {
        int v = t >> 6, oo = t & 63;
        Zsm[t] = g_Z[(size_t)(h * NV + v) * OB + obt * 64 + oo];
    }
    __syncthreads();

    float Sc[7], Ss[7];
#pragma unroll
    for (int j = 0; j < 7; j++) { Sc[j] = Ss[j] = 0.f; }

#pragma unroll 3
    for (int v = 1; v < 28; v++) {
        float2 z = Zsm[v * 64 + obl];
#pragma unroll
        for (int j = 0; j < 7; j++) {
            float2 c = FsC[(wg * 7 + j) * 27 + v - 1];
            Sc[j] += z.x * c.x;
            Ss[j] += z.y * c.y;
        }
    }

    float z0  = Zsm[obl].x;
    float z28 = Zsm[28 * 64 + obl].x;
    const float sInv = 1.0f / (float)HW;
#pragma unroll
    for (int j = 0; j < 7; j++) {
        int s = wg * 7 + j;
        if (s < 27) {
            int w = s + 1;
            float par = (w & 1) ? -z28 : z28;
            float base = z0 + par;
            Ysm[w * 65 + obl]        = (base + 2.0f * (Sc[j] - Ss[j])) * sInv;
            Ysm[(NN - w) * 65 + obl] = (base + 2.0f * (Sc[j] + Ss[j])) * sInv;
        }
    }
    if (wg == 3) {   // slot 27: w=0 and w=28
        float a0 = 0.f, a28 = 0.f;
        for (int v = 1; v < 28; v++) {
            float zr = Zsm[v * 64 + obl].x;
            a0 += zr;
            a28 += (v & 1) ? -zr : zr;
        }
        Ysm[0 * 65 + obl]  = (z0 + z28 + 2.0f * a0)  * sInv;
        Ysm[28 * 65 + obl] = (z0 + z28 + 2.0f * a28) * sInv;
    }
    __syncthreads();

    for (int t = tid; t < NN * 64; t += 256) {
        int lob = t / NN, w = t - lob * NN;
        int ob = obt * 64 + lob;
        int o = ob >> 5, bb = ob & 31;
        out[(size_t)(bb * CO + o) * HW + h * NN + w] = Ysm[w * 65 + lob] + bias[o];
    }
}

// ---------------- launch -----------------------------------------------------
extern "C" void kernel_launch(void* const* d_in, const int* in_sizes, int n_in,
                              void* d_out, int out_size) {
    const float* x    = (const float*)d_in[0];   // [32,64,56,56]
    const float* kr   = (const float*)d_in[1];   // [128,64,56,56]
    const float* ki   = (const float*)d_in[2];   // [128,64,56,56]
    const float* bias = (const float*)d_in[3];   // [128]
    float* out = (float*)d_out;                  // [32,128,56,56]

    const int smem_fwd = HW * (int)sizeof(float)
                       + (29 * NN + NN * 30 + NN * 28) * (int)sizeof(float2);
    const int smem_iu  = (28 * 27 + NN * 64) * (int)sizeof(float2);
    const int smem_iv  = (28 * 27 + NV * 64) * (int)sizeof(float2) + NN * 65 * (int)sizeof(float);
    cudaFuncSetAttribute(k_fwd_fft, cudaFuncAttributeMaxDynamicSharedMemorySize, smem_fwd);
    cudaFuncSetAttribute(k_ifft_u, cudaFuncAttributeMaxDynamicSharedMemorySize, smem_iu);
    cudaFuncSetAttribute(k_ifft_v_out, cudaFuncAttributeMaxDynamicSharedMemorySize, smem_iv);

    k_init_F<<<(HW + 255) / 256, 256>>>();
    k_transpose_K<<<dim3((NF + 31) / 32, OI / 32), dim3(32, 8)>>>(kr, ki);
    k_fwd_fft<<<IB, 256, smem_fwd>>>(x);
    k_einsum<<<NF, 256>>>();
    k_ifft_u<<<dim3(64, NV), 256, smem_iu>>>();
    k_ifft_v_out<<<dim3(64, NN), 256, smem_iv>>>(bias, out);
}

// round 9
// speedup vs baseline: 3.0140x; 1.1296x over previous
#include <cuda_runtime.h>
#include <math_constants.h>
#include <cstdint>

// Problem constants
#define NN 56
#define HW 3136          // 56*56
#define NV 29            // rfft columns: v in [0,28]
#define NF (NN*NV)       // 1624 retained frequencies
#define NB 32            // batch
#define CI 64
#define CO 128
#define OB 4096          // CO*NB
#define IB 2048          // CI*NB
#define OI 8192          // CO*CI
#define PADK 132         // padded K stride for mma SMEM tiles

// ---------------- scratch (device globals; no runtime allocation allowed) ----
__device__ __align__(16) float2 g_F [HW];                   // twiddles
__device__ __align__(16) float  g_KA[(size_t)NF * 16384];   // [f][o][k=2i+c] tf32  106MB
__device__ __align__(16) float2 g_Xf[(size_t)NF * IB];      // [f][i*32+b]           27MB
__device__ __align__(16) float2 g_Yf[(size_t)NF * OB];      // [f][o*32+b]           53MB
__device__ __align__(16) float2 g_Z [(size_t)NF * OB];      // [h*29+v][ob]          53MB

__device__ __forceinline__ float f2tf32(float x) {
    uint32_t u;
    asm("cvt.rna.tf32.f32 %0, %1;" : "=r"(u) : "f"(x));
    return __uint_as_float(u);
}

// ---------------- 0) twiddle init -------------------------------------------
__global__ void k_init_F() {
    int idx = blockIdx.x * blockDim.x + threadIdx.x;
    if (idx < HW) {
        int j = idx / NN, k = idx % NN;
        int m = (j * k) % NN;
        float ang = -2.0f * CUDART_PI_F * (float)m / (float)NN;
        float s, c;
        sincosf(ang, &s, &c);
        g_F[idx] = make_float2(c, s);
    }
}

// ------- 1) build A tiles: g_KA[f][o][k], k=2i+c interleaved, tf32-rounded ---
__global__ void k_build_KA(const float* __restrict__ kr, const float* __restrict__ ki) {
    __shared__ float2 tile[32][33];     // [i_local][f_local]
    int fi0 = blockIdx.x * 32;
    int oi0 = blockIdx.y * 32;          // one o (oi0/64), i0 = oi0%64 (0 or 32)
    int tx = threadIdx.x, ty = threadIdx.y;
    int fi = fi0 + tx;
    bool valid = fi < NF;
    int u = fi / NV, v = fi - u * NV;
    int fsrc = u * NN + v;
#pragma unroll
    for (int k = 0; k < 4; k++) {
        int oi = oi0 + ty + k * 8;
        if (valid) {
            size_t src = (size_t)oi * HW + fsrc;
            tile[ty + k * 8][tx] = make_float2(kr[src], ki[src]);
        }
    }
    __syncthreads();

    int t = ty * 32 + tx;
    int f_local = t >> 3;
    int f = fi0 + f_local;
    if (f < NF) {
        int o  = oi0 >> 6;
        int i0 = oi0 & 63;
        float* dst = g_KA + (size_t)f * 16384 + o * 128 + 2 * i0;
        int c0 = (t & 7) * 4;
#pragma unroll
        for (int r = 0; r < 4; r++) {
            int il = c0 + r;
            float2 kv = tile[il][f_local];
            *(float2*)(dst + 2 * il) = make_float2(f2tf32(kv.x), f2tf32(kv.y));
        }
    }
}

// ------- 2) forward rfft2 per (b,i), conjugate-pair factorized ---------------
__global__ void k_fwd_fft(const float* __restrict__ x) {
    extern __shared__ char smem[];
    float*  xs  = (float*)smem;                            // [3136]
    float2* Fs  = (float2*)(smem + HW * sizeof(float));    // [29][56]
    float2* A1  = Fs + 29 * NN;                            // [56][30]
    float2* sdm = A1 + NN * 30;                            // [56][28]

    int bi = blockIdx.x;
    int b  = bi / CI, ci = bi % CI;
    int tid = threadIdx.x;

    for (int t = tid; t < 29 * NN; t += 256) Fs[t] = g_F[t];
    for (int t = tid; t < HW; t += 256) xs[t] = x[(size_t)bi * HW + t];
    __syncthreads();

    for (int t = tid; t < NN * 28; t += 256) {
        int h = t / 28, w = t - h * 28;
        const float* xr = xs + h * NN;
        sdm[t] = (w == 0) ? make_float2(xr[0], xr[28])
                          : make_float2(xr[w] + xr[NN - w], xr[w] - xr[NN - w]);
    }
    __syncthreads();

    int lane = tid & 31;
    int grp  = tid >> 5;

    {   // stage a
        float ar[7], ai[7];
        float sgn = (lane & 1) ? -1.f : 1.f;
#pragma unroll
        for (int j = 0; j < 7; j++) {
            float2 sd0 = sdm[(grp * 7 + j) * 28];
            ar[j] = sd0.x + sgn * sd0.y;
            ai[j] = 0.f;
        }
        for (int w = 1; w < 28; w++) {
            float2 fv = Fs[w * NN + lane];
#pragma unroll
            for (int j = 0; j < 7; j++) {
                float2 sd = sdm[(grp * 7 + j) * 28 + w];
                ar[j] += fv.x * sd.x;
                ai[j] += fv.y * sd.y;
            }
        }
        if (lane < NV) {
#pragma unroll
            for (int j = 0; j < 7; j++)
                A1[(grp * 7 + j) * 30 + lane] = make_float2(ar[j], ai[j]);
        }
    }
    __syncthreads();

    {   // stage b: u-pairs via separated sums
        float Sap[4], Sbq[4], Saq[4], Sbp[4];
#pragma unroll
        for (int j = 0; j < 4; j++) { Sap[j] = Sbq[j] = Saq[j] = Sbp[j] = 0.f; }
        for (int h = 0; h < NN; h++) {
            float2 av = A1[h * 30 + lane];
#pragma unroll
            for (int j = 0; j < 4; j++) {
                int p = grp + 8 * j;
                float2 fv = Fs[(p & 31) * NN + h];   // p>28 discarded; in-bounds of smem
                Sap[j] += fv.x * av.x;
                Sbq[j] += fv.y * av.y;
                Saq[j] += fv.x * av.y;
                Sbp[j] += fv.y * av.x;
            }
        }
        if (lane < NV) {
            int col = ci * NB + b;
#pragma unroll
            for (int j = 0; j < 4; j++) {
                int p = grp + 8 * j;
                if (p <= 28) {
                    g_Xf[(size_t)(p * NV + lane) * IB + col] =
                        make_float2(Sap[j] - Sbq[j], Saq[j] + Sbp[j]);
                    if (p != 0 && p != 28)
                        g_Xf[(size_t)((NN - p) * NV + lane) * IB + col] =
                            make_float2(Sap[j] + Sbq[j], Saq[j] - Sbp[j]);
                }
            }
        }
    }
}

// ------- 3) mma.sync tf32 einsum: D[o][n=2b+d] = sum_k A[o][k] B[n][k] -------
__global__ void __launch_bounds__(256, 2) k_einsum_mma() {
    extern __shared__ char smem[];
    float* As = (float*)smem;              // [128][PADK]
    float* Bs = (float*)smem + 128 * PADK; // [64][PADK]
    int f = blockIdx.x;
    int tid = threadIdx.x;
    int wid = tid >> 5, lane = tid & 31;
    int gid = lane >> 2, tig = lane & 3;

    // load A tile (pre-rounded tf32)
    {
        const float4* Ag = (const float4*)(g_KA + (size_t)f * 16384);
#pragma unroll 4
        for (int t = tid; t < 4096; t += 256) {
            int row = t >> 5, ch = t & 31;
            *(float4*)(As + row * PADK + ch * 4) = Ag[t];
        }
    }
    // build B tile: row 2b = (Xr, -Xi) interleaved over k=2i+c; row 2b+1 = (Xi, Xr)
    {
        const float4* Xg = (const float4*)(g_Xf + (size_t)f * IB);
#pragma unroll 2
        for (int t = tid; t < 1024; t += 256) {
            float4 xv = Xg[t];                // complex pair: (i, b) and (i, b+1)
            int e = 2 * t;
            int i = e >> 5, b = e & 31;       // b even
            float xr0 = f2tf32(xv.x), xi0 = f2tf32(xv.y);
            float xr1 = f2tf32(xv.z), xi1 = f2tf32(xv.w);
            int k = 2 * i;
            float* r0 = Bs + (2 * b) * PADK + k;
            *(float2*)r0              = make_float2(xr0, -xi0);
            *(float2*)(r0 + PADK)     = make_float2(xi0, xr0);
            *(float2*)(r0 + 2 * PADK) = make_float2(xr1, -xi1);
            *(float2*)(r0 + 3 * PADK) = make_float2(xi1, xr1);
        }
    }
    __syncthreads();

    int m0 = wid * 16;
    float acc[8][4];
#pragma unroll
    for (int j = 0; j < 8; j++)
#pragma unroll
        for (int q = 0; q < 4; q++) acc[j][q] = 0.f;

    const float* Ar0 = As + (m0 + gid) * PADK + tig;
    const float* Ar1 = As + (m0 + gid + 8) * PADK + tig;
    const float* Br  = Bs + gid * PADK + tig;

#pragma unroll
    for (int kc = 0; kc < 16; kc++) {
        int k0 = kc * 8;
        uint32_t a0 = __float_as_uint(Ar0[k0]);
        uint32_t a1 = __float_as_uint(Ar1[k0]);
        uint32_t a2 = __float_as_uint(Ar0[k0 + 4]);
        uint32_t a3 = __float_as_uint(Ar1[k0 + 4]);
#pragma unroll
        for (int j = 0; j < 8; j++) {
            uint32_t b0 = __float_as_uint(Br[j * 8 * PADK + k0]);
            uint32_t b1 = __float_as_uint(Br[j * 8 * PADK + k0 + 4]);
            asm volatile(
                "mma.sync.aligned.m16n8k8.row.col.f32.tf32.tf32.f32 "
                "{%0,%1,%2,%3}, {%4,%5,%6,%7}, {%8,%9}, {%0,%1,%2,%3};"
                : "+f"(acc[j][0]), "+f"(acc[j][1]), "+f"(acc[j][2]), "+f"(acc[j][3])
                : "r"(a0), "r"(a1), "r"(a2), "r"(a3), "r"(b0), "r"(b1));
        }
    }

    // C frag: c0/c1 = (Yr,Yi) at row gid (o), col-pair b = 4j+tig; c2/c3 at row gid+8
    float2* Yf = g_Yf + (size_t)f * OB;
#pragma unroll
    for (int j = 0; j < 8; j++) {
        int b = 4 * j + tig;
        Yf[(m0 + gid) * NB + b]     = make_float2(acc[j][0], acc[j][1]);
        Yf[(m0 + gid + 8) * NB + b] = make_float2(acc[j][2], acc[j][3]);
    }
}

// ------- 4) inverse over u, double conjugate-pair ----------------------------
__global__ void k_ifft_u() {
    extern __shared__ char smem[];
    float2* Fc  = (float2*)smem;      // [28][27]
    float2* Ysm = Fc + 28 * 27;       // [56][64]
    int v   = blockIdx.y;
    int obt = blockIdx.x;
    int tid = threadIdx.x;
    int wg  = tid >> 6;
    int obl = tid & 63;

    for (int t = tid; t < 28 * 27; t += 256) {
        int s = t / 27, u = t - s * 27 + 1;
        if (s < 27) {
            float2 f = g_F[(s + 1) * NN + u];
            Fc[t] = make_float2(f.x, -f.y);
        } else {
            Fc[t] = make_float2(0.f, 0.f);
        }
    }
    for (int t = tid; t < NN * 64; t += 256) {
        int uu = t >> 6, oo = t & 63;
        Ysm[t] = g_Yf[(size_t)(uu * NV + v) * OB + obt * 64 + oo];
    }
    __syncthreads();

    float2 Y0  = Ysm[obl];
    float2 Y28 = Ysm[28 * 64 + obl];

    float S1[7], S2[7], S3[7], S4[7];
#pragma unroll
    for (int j = 0; j < 7; j++) { S1[j] = S2[j] = S3[j] = S4[j] = 0.f; }

#pragma unroll 3
    for (int up = 1; up < 28; up++) {
        float2 Yu = Ysm[up * 64 + obl];
        float2 Ym = Ysm[(NN - up) * 64 + obl];
        float Px = Yu.x + Ym.x, Py = Yu.y + Ym.y;
        float Mx = Yu.x - Ym.x, My = Yu.y - Ym.y;
#pragma unroll
        for (int j = 0; j < 7; j++) {
            float2 c = Fc[(wg * 7 + j) * 27 + up - 1];
            S1[j] += c.x * Px;
            S2[j] += c.y * My;
            S3[j] += c.x * Py;
            S4[j] += c.y * Mx;
        }
    }

    int ob = obt * 64 + obl;
#pragma unroll
    for (int j = 0; j < 7; j++) {
        int s = wg * 7 + j;
        if (s < 27) {
            int h = s + 1;
            float sg = (h & 1) ? -1.f : 1.f;
            float bx = Y0.x + sg * Y28.x, by = Y0.y + sg * Y28.y;
            g_Z[(size_t)(h * NV + v) * OB + ob] =
                make_float2(bx + S1[j] - S2[j], by + S3[j] + S4[j]);
            g_Z[(size_t)((NN - h) * NV + v) * OB + ob] =
                make_float2(bx + S1[j] + S2[j], by + S3[j] - S4[j]);
        }
    }
    if (wg == 3) {
        float2 a0 = make_float2(Y0.x + Y28.x, Y0.y + Y28.y);
        float2 a28 = a0;
        for (int up = 1; up < 28; up++) {
            float2 Yu = Ysm[up * 64 + obl];
            float2 Ym = Ysm[(NN - up) * 64 + obl];
            float Px = Yu.x + Ym.x, Py = Yu.y + Ym.y;
            float sg = (up & 1) ? -1.f : 1.f;
            a0.x += Px;        a0.y += Py;
            a28.x += sg * Px;  a28.y += sg * Py;
        }
        g_Z[(size_t)(0 * NV + v) * OB + ob]  = a0;
        g_Z[(size_t)(28 * NV + v) * OB + ob] = a28;
    }
}

// ------- 5) Hermitian inverse over v, w-paired, + bias + final layout --------
__global__ void k_ifft_v_out(const float* __restrict__ bias, float* __restrict__ out) {
    extern __shared__ char smem[];
    float2* FsC = (float2*)smem;               // [28][27]
    float2* Zsm = FsC + 28 * 27;               // [29][64]
    float*  Ysm = (float*)(Zsm + NV * 64);     // [56][65]
    int h   = blockIdx.y;
    int obt = blockIdx.x;
    int tid = threadIdx.x;
    int wg  = tid >> 6;
    int obl = tid & 63;

    for (int t = tid; t < 28 * 27; t += 256) {
        int s = t / 27, v = t - s * 27 + 1;
        if (s < 27) {
            float2 f = g_F[(s + 1) * NN + v];
            FsC[t] = make_float2(f.x, -f.y);
        } else {
            FsC[t] = make_float2(0.f, 0.f);
        }
    }
    for (int t = tid; t < NV * 64; t += 256) {
        int v = t >> 6, oo = t & 63;
        Zsm[t] = g_Z[(size_t)(h * NV + v) * OB + obt * 64 + oo];
    }
    __syncthreads();

    float Sc[7], Ss[7];
#pragma unroll
    for (int j = 0; j < 7; j++) { Sc[j] = Ss[j] = 0.f; }

#pragma unroll 3
    for (int v = 1; v < 28; v++) {
        float2 z = Zsm[v * 64 + obl];
#pragma unroll
        for (int j = 0; j < 7; j++) {
            float2 c = FsC[(wg * 7 + j) * 27 + v - 1];
            Sc[j] += z.x * c.x;
            Ss[j] += z.y * c.y;
        }
    }

    float z0  = Zsm[obl].x;
    float z28 = Zsm[28 * 64 + obl].x;
    const float sInv = 1.0f / (float)HW;
#pragma unroll
    for (int j = 0; j < 7; j++) {
        int s = wg * 7 + j;
        if (s < 27) {
            int w = s + 1;
            float par = (w & 1) ? -z28 : z28;
            float base = z0 + par;
            Ysm[w * 65 + obl]        = (base + 2.0f * (Sc[j] - Ss[j])) * sInv;
            Ysm[(NN - w) * 65 + obl] = (base + 2.0f * (Sc[j] + Ss[j])) * sInv;
        }
    }
    if (wg == 3) {
        float a0 = 0.f, a28 = 0.f;
        for (int v = 1; v < 28; v++) {
            float zr = Zsm[v * 64 + obl].x;
            a0 += zr;
            a28 += (v & 1) ? -zr : zr;
        }
        Ysm[0 * 65 + obl]  = (z0 + z28 + 2.0f * a0)  * sInv;
        Ysm[28 * 65 + obl] = (z0 + z28 + 2.0f * a28) * sInv;
    }
    __syncthreads();

    // ob = o*32 + b
    for (int t = tid; t < NN * 64; t += 256) {
        int lob = t / NN, w = t - lob * NN;
        int ob = obt * 64 + lob;
        int o = ob >> 5, bb = ob & 31;
        out[(size_t)(bb * CO + o) * HW + h * NN + w] = Ysm[w * 65 + lob] + bias[o];
    }
}

// ---------------- launch -----------------------------------------------------
extern "C" void kernel_launch(void* const* d_in, const int* in_sizes, int n_in,
                              void* d_out, int out_size) {
    const float* x    = (const float*)d_in[0];   // [32,64,56,56]
    const float* kr   = (const float*)d_in[1];   // [128,64,56,56]
    const float* ki   = (const float*)d_in[2];   // [128,64,56,56]
    const float* bias = (const float*)d_in[3];   // [128]
    float* out = (float*)d_out;                  // [32,128,56,56]

    const int smem_fwd = HW * (int)sizeof(float)
                       + (29 * NN + NN * 30 + NN * 28) * (int)sizeof(float2);
    const int smem_mma = (128 + 64) * PADK * (int)sizeof(float);     // 101376
    const int smem_iu  = (28 * 27 + NN * 64) * (int)sizeof(float2);
    const int smem_iv  = (28 * 27 + NV * 64) * (int)sizeof(float2) + NN * 65 * (int)sizeof(float);
    cudaFuncSetAttribute(k_fwd_fft, cudaFuncAttributeMaxDynamicSharedMemorySize, smem_fwd);
    cudaFuncSetAttribute(k_einsum_mma, cudaFuncAttributeMaxDynamicSharedMemorySize, smem_mma);
    cudaFuncSetAttribute(k_ifft_u, cudaFuncAttributeMaxDynamicSharedMemorySize, smem_iu);
    cudaFuncSetAttribute(k_ifft_v_out, cudaFuncAttributeMaxDynamicSharedMemorySize, smem_iv);

    k_init_F<<<(HW + 255) / 256, 256>>>();
    k_build_KA<<<dim3((NF + 31) / 32, OI / 32), dim3(32, 8)>>>(kr, ki);
    k_fwd_fft<<<IB, 256, smem_fwd>>>(x);
    k_einsum_mma<<<NF, 256, smem_mma>>>();
    k_ifft_u<<<dim3(64, NV), 256, smem_iu>>>();
    k_ifft_v_out<<<dim3(64, NN), 256, smem_iv>>>(bias, out);
}

// round 10
// speedup vs baseline: 3.4503x; 1.1448x over previous
#include <cuda_runtime.h>
#include <cuda_fp16.h>
#include <math_constants.h>
#include <cstdint>

// Problem constants
#define NN 56
#define HW 3136          // 56*56
#define NV 29            // rfft columns: v in [0,28]
#define NF (NN*NV)       // 1624 retained frequencies
#define NB 32            // batch
#define CI 64
#define CO 128
#define OB 4096          // CO*NB
#define IB 2048          // CI*NB
#define OI 8192          // CO*CI
#define PADH 136         // padded K stride (halfs) for mma SMEM tiles

// ---------------- scratch (device globals; no runtime allocation allowed) ----
__device__ __align__(16) float2  g_F [HW];                   // twiddles
__device__ __align__(16) __half  g_KA[(size_t)NF * 16384];   // [f][o][k=2i+c] fp16  53MB
__device__ __align__(16) __half2 g_Xf[(size_t)NF * IB];      // [f][i*32+b] cplx     13MB
__device__ __align__(16) float2  g_Yf[(size_t)NF * OB];      // [f][o*32+b]          53MB
__device__ __align__(16) float2  g_Z [(size_t)NF * OB];      // [h*29+v][ob]         53MB

// ---------------- 0) twiddle init -------------------------------------------
__global__ void k_init_F() {
    int idx = blockIdx.x * blockDim.x + threadIdx.x;
    if (idx < HW) {
        int j = idx / NN, k = idx % NN;
        int m = (j * k) % NN;
        float ang = -2.0f * CUDART_PI_F * (float)m / (float)NN;
        float s, c;
        sincosf(ang, &s, &c);
        g_F[idx] = make_float2(c, s);
    }
}

// ------- 1) build A tiles: g_KA[f][o][k], k=2i+c interleaved, fp16 -----------
__global__ void k_build_KA(const float* __restrict__ kr, const float* __restrict__ ki) {
    __shared__ float2 tile[32][33];     // [i_local][f_local]
    int fi0 = blockIdx.x * 32;
    int oi0 = blockIdx.y * 32;          // one o (oi0/64), i0 = oi0%64 (0 or 32)
    int tx = threadIdx.x, ty = threadIdx.y;
    int fi = fi0 + tx;
    bool valid = fi < NF;
    int u = fi / NV, v = fi - u * NV;
    int fsrc = u * NN + v;
#pragma unroll
    for (int k = 0; k < 4; k++) {
        int oi = oi0 + ty + k * 8;
        if (valid) {
            size_t src = (size_t)oi * HW + fsrc;
            tile[ty + k * 8][tx] = make_float2(kr[src], ki[src]);
        }
    }
    __syncthreads();

    int t = ty * 32 + tx;
    int f_local = t >> 3;
    int f = fi0 + f_local;
    if (f < NF) {
        int o  = oi0 >> 6;
        int i0 = oi0 & 63;
        __half2* dst = (__half2*)(g_KA + (size_t)f * 16384 + o * 128 + 2 * i0);
        int c0 = (t & 7) * 4;
#pragma unroll
        for (int r = 0; r < 4; r++) {
            int il = c0 + r;
            float2 kv = tile[il][f_local];
            dst[il] = __floats2half2_rn(kv.x, kv.y);
        }
    }
}

// ------- 2) forward rfft2 per (b,i), conjugate-pair factorized ---------------
__global__ void k_fwd_fft(const float* __restrict__ x) {
    extern __shared__ char smem[];
    float*  xs  = (float*)smem;                            // [3136]
    float2* Fs  = (float2*)(smem + HW * sizeof(float));    // [29][56]
    float2* A1  = Fs + 29 * NN;                            // [56][30]
    float2* sdm = A1 + NN * 30;                            // [56][28]

    int bi = blockIdx.x;
    int b  = bi / CI, ci = bi % CI;
    int tid = threadIdx.x;

    for (int t = tid; t < 29 * NN; t += 256) Fs[t] = g_F[t];
    for (int t = tid; t < HW; t += 256) xs[t] = x[(size_t)bi * HW + t];
    __syncthreads();

    for (int t = tid; t < NN * 28; t += 256) {
        int h = t / 28, w = t - h * 28;
        const float* xr = xs + h * NN;
        sdm[t] = (w == 0) ? make_float2(xr[0], xr[28])
                          : make_float2(xr[w] + xr[NN - w], xr[w] - xr[NN - w]);
    }
    __syncthreads();

    int lane = tid & 31;
    int grp  = tid >> 5;

    {   // stage a
        float ar[7], ai[7];
        float sgn = (lane & 1) ? -1.f : 1.f;
#pragma unroll
        for (int j = 0; j < 7; j++) {
            float2 sd0 = sdm[(grp * 7 + j) * 28];
            ar[j] = sd0.x + sgn * sd0.y;
            ai[j] = 0.f;
        }
        for (int w = 1; w < 28; w++) {
            float2 fv = Fs[w * NN + lane];
#pragma unroll
            for (int j = 0; j < 7; j++) {
                float2 sd = sdm[(grp * 7 + j) * 28 + w];
                ar[j] += fv.x * sd.x;
                ai[j] += fv.y * sd.y;
            }
        }
        if (lane < NV) {
#pragma unroll
            for (int j = 0; j < 7; j++)
                A1[(grp * 7 + j) * 30 + lane] = make_float2(ar[j], ai[j]);
        }
    }
    __syncthreads();

    {   // stage b: u-pairs via separated sums
        float Sap[4], Sbq[4], Saq[4], Sbp[4];
#pragma unroll
        for (int j = 0; j < 4; j++) { Sap[j] = Sbq[j] = Saq[j] = Sbp[j] = 0.f; }
        for (int h = 0; h < NN; h++) {
            float2 av = A1[h * 30 + lane];
#pragma unroll
            for (int j = 0; j < 4; j++) {
                int p = grp + 8 * j;
                float2 fv = Fs[(p & 31) * NN + h];   // p>28 discarded; in-bounds of smem
                Sap[j] += fv.x * av.x;
                Sbq[j] += fv.y * av.y;
                Saq[j] += fv.x * av.y;
                Sbp[j] += fv.y * av.x;
            }
        }
        if (lane < NV) {
            int col = ci * NB + b;
#pragma unroll
            for (int j = 0; j < 4; j++) {
                int p = grp + 8 * j;
                if (p <= 28) {
                    g_Xf[(size_t)(p * NV + lane) * IB + col] =
                        __floats2half2_rn(Sap[j] - Sbq[j], Saq[j] + Sbp[j]);
                    if (p != 0 && p != 28)
                        g_Xf[(size_t)((NN - p) * NV + lane) * IB + col] =
                            __floats2half2_rn(Sap[j] + Sbq[j], Saq[j] - Sbp[j]);
                }
            }
        }
    }
}

// ------- 3) mma.sync fp16 einsum: D[o][n=2b+d] = sum_k A[o][k] B[n][k] -------
__global__ void __launch_bounds__(256, 3) k_einsum_mma() {
    extern __shared__ char smem[];
    __half* As = (__half*)smem;               // [128][PADH]
    __half* Bs = (__half*)smem + 128 * PADH;  // [64][PADH]
    int f = blockIdx.x;
    int tid = threadIdx.x;
    int wid = tid >> 5, lane = tid & 31;
    int gid = lane >> 2, tig = lane & 3;

    // load A tile (fp16, 32KB = 2048 uint4)
    {
        const uint4* Ag = (const uint4*)(g_KA + (size_t)f * 16384);
#pragma unroll 4
        for (int t = tid; t < 2048; t += 256) {
            int row = t >> 4, ch = t & 15;
            *(uint4*)(As + row * PADH + ch * 8) = Ag[t];
        }
    }
    // build B tile: row 2b = (Xr, -Xi) interleaved over k=2i+c; row 2b+1 = (Xi, Xr)
    {
        const __half2* Xg = g_Xf + (size_t)f * IB;
#pragma unroll 4
        for (int t = tid; t < 2048; t += 256) {
            __half2 xv = Xg[t];
            int i = t >> 5, b = t & 31;
            __half xr = __low2half(xv), xi = __high2half(xv);
            __half2* r0 = (__half2*)(Bs + (2 * b) * PADH + 2 * i);
            r0[0]          = __halves2half2(xr, __hneg(xi));
            *(__half2*)((__half*)r0 + PADH) = __halves2half2(xi, xr);
        }
    }
    __syncthreads();

    int m0 = wid * 16;
    float acc[8][4];
#pragma unroll
    for (int j = 0; j < 8; j++)
#pragma unroll
        for (int q = 0; q < 4; q++) acc[j][q] = 0.f;

    const __half* Ar0 = As + (m0 + gid) * PADH + 2 * tig;
    const __half* Ar1 = Ar0 + 8 * PADH;
    const __half* Br  = Bs + gid * PADH + 2 * tig;

#pragma unroll
    for (int kc = 0; kc < 8; kc++) {
        int k0 = kc * 16;
        uint32_t a0 = *(const uint32_t*)(Ar0 + k0);
        uint32_t a1 = *(const uint32_t*)(Ar1 + k0);
        uint32_t a2 = *(const uint32_t*)(Ar0 + k0 + 8);
        uint32_t a3 = *(const uint32_t*)(Ar1 + k0 + 8);
#pragma unroll
        for (int j = 0; j < 8; j++) {
            uint32_t b0 = *(const uint32_t*)(Br + j * 8 * PADH + k0);
            uint32_t b1 = *(const uint32_t*)(Br + j * 8 * PADH + k0 + 8);
            asm volatile(
                "mma.sync.aligned.m16n8k16.row.col.f32.f16.f16.f32 "
                "{%0,%1,%2,%3}, {%4,%5,%6,%7}, {%8,%9}, {%0,%1,%2,%3};"
                : "+f"(acc[j][0]), "+f"(acc[j][1]), "+f"(acc[j][2]), "+f"(acc[j][3])
                : "r"(a0), "r"(a1), "r"(a2), "r"(a3), "r"(b0), "r"(b1));
        }
    }

    // C frag: c0/c1 = (Yr,Yi) at row gid (o), b = 4j+tig; c2/c3 at row gid+8
    float2* Yf = g_Yf + (size_t)f * OB;
#pragma unroll
    for (int j = 0; j < 8; j++) {
        int b = 4 * j + tig;
        Yf[(m0 + gid) * NB + b]     = make_float2(acc[j][0], acc[j][1]);
        Yf[(m0 + gid + 8) * NB + b] = make_float2(acc[j][2], acc[j][3]);
    }
}

// ------- 4) inverse over u, double conjugate-pair ----------------------------
__global__ void k_ifft_u() {
    extern __shared__ char smem[];
    float2* Fc  = (float2*)smem;      // [28][27]
    float2* Ysm = Fc + 28 * 27;       // [56][64]
    int v   = blockIdx.y;
    int obt = blockIdx.x;
    int tid = threadIdx.x;
    int wg  = tid >> 6;
    int obl = tid & 63;

    for (int t = tid; t < 28 * 27; t += 256) {
        int s = t / 27, u = t - s * 27 + 1;
        if (s < 27) {
            float2 f = g_F[(s + 1) * NN + u];
            Fc[t] = make_float2(f.x, -f.y);
        } else {
            Fc[t] = make_float2(0.f, 0.f);
        }
    }
    for (int t = tid; t < NN * 64; t += 256) {
        int uu = t >> 6, oo = t & 63;
        Ysm[t] = g_Yf[(size_t)(uu * NV + v) * OB + obt * 64 + oo];
    }
    __syncthreads();

    float2 Y0  = Ysm[obl];
    float2 Y28 = Ysm[28 * 64 + obl];

    float S1[7], S2[7], S3[7], S4[7];
#pragma unroll
    for (int j = 0; j < 7; j++) { S1[j] = S2[j] = S3[j] = S4[j] = 0.f; }

#pragma unroll 3
    for (int up = 1; up < 28; up++) {
        float2 Yu = Ysm[up * 64 + obl];
        float2 Ym = Ysm[(NN - up) * 64 + obl];
        float Px = Yu.x + Ym.x, Py = Yu.y + Ym.y;
        float Mx = Yu.x - Ym.x, My = Yu.y - Ym.y;
#pragma unroll
        for (int j = 0; j < 7; j++) {
            float2 c = Fc[(wg * 7 + j) * 27 + up - 1];
            S1[j] += c.x * Px;
            S2[j] += c.y * My;
            S3[j] += c.x * Py;
            S4[j] += c.y * Mx;
        }
    }

    int ob = obt * 64 + obl;
#pragma unroll
    for (int j = 0; j < 7; j++) {
        int s = wg * 7 + j;
        if (s < 27) {
            int h = s + 1;
            float sg = (h & 1) ? -1.f : 1.f;
            float bx = Y0.x + sg * Y28.x, by = Y0.y + sg * Y28.y;
            g_Z[(size_t)(h * NV + v) * OB + ob] =
                make_float2(bx + S1[j] - S2[j], by + S3[j] + S4[j]);
            g_Z[(size_t)((NN - h) * NV + v) * OB + ob] =
                make_float2(bx + S1[j] + S2[j], by + S3[j] - S4[j]);
        }
    }
    if (wg == 3) {
        float2 a0 = make_float2(Y0.x + Y28.x, Y0.y + Y28.y);
        float2 a28 = a0;
        for (int up = 1; up < 28; up++) {
            float2 Yu = Ysm[up * 64 + obl];
            float2 Ym = Ysm[(NN - up) * 64 + obl];
            float Px = Yu.x + Ym.x, Py = Yu.y + Ym.y;
            float sg = (up & 1) ? -1.f : 1.f;
            a0.x += Px;        a0.y += Py;
            a28.x += sg * Px;  a28.y += sg * Py;
        }
        g_Z[(size_t)(0 * NV + v) * OB + ob]  = a0;
        g_Z[(size_t)(28 * NV + v) * OB + ob] = a28;
    }
}

// ------- 5) Hermitian inverse over v, w-paired, + bias + final layout --------
__global__ void k_ifft_v_out(const float* __restrict__ bias, float* __restrict__ out) {
    extern __shared__ char smem[];
    float2* FsC = (float2*)smem;               // [28][27]
    float2* Zsm = FsC + 28 * 27;               // [29][64]
    float*  Ysm = (float*)(Zsm + NV * 64);     // [56][65]
    int h   = blockIdx.y;
    int obt = blockIdx.x;
    int tid = threadIdx.x;
    int wg  = tid >> 6;
    int obl = tid & 63;

    for (int t = tid; t < 28 * 27; t += 256) {
        int s = t / 27, v = t - s * 27 + 1;
        if (s < 27) {
            float2 f = g_F[(s + 1) * NN + v];
            FsC[t] = make_float2(f.x, -f.y);
        } else {
            FsC[t] = make_float2(0.f, 0.f);
        }
    }
    for (int t = tid; t < NV * 64; t += 256) {
        int v = t >> 6, oo = t & 63;
        Zsm[t] = g_Z[(size_t)(h * NV + v) * OB + obt * 64 + oo];
    }
    __syncthreads();

    float Sc[7], Ss[7];
#pragma unroll
    for (int j = 0; j < 7; j++) { Sc[j] = Ss[j] = 0.f; }

#pragma unroll 3
    for (int v = 1; v < 28; v++) {
        float2 z = Zsm[v * 64 + obl];
#pragma unroll
        for (int j = 0; j < 7; j++) {
            float2 c = FsC[(wg * 7 + j) * 27 + v - 1];
            Sc[j] += z.x * c.x;
            Ss[j] += z.y * c.y;
        }
    }

    float z0  = Zsm[obl].x;
    float z28 = Zsm[28 * 64 + obl].x;
    const float sInv = 1.0f / (float)HW;
#pragma unroll
    for (int j = 0; j < 7; j++) {
        int s = wg * 7 + j;
        if (s < 27) {
            int w = s + 1;
            float par = (w & 1) ? -z28 : z28;
            float base = z0 + par;
            Ysm[w * 65 + obl]        = (base + 2.0f * (Sc[j] - Ss[j])) * sInv;
            Ysm[(NN - w) * 65 + obl] = (base + 2.0f * (Sc[j] + Ss[j])) * sInv;
        }
    }
    if (wg == 3) {
        float a0 = 0.f, a28 = 0.f;
        for (int v = 1; v < 28; v++) {
            float zr = Zsm[v * 64 + obl].x;
            a0 += zr;
            a28 += (v & 1) ? -zr : zr;
        }
        Ysm[0 * 65 + obl]  = (z0 + z28 + 2.0f * a0)  * sInv;
        Ysm[28 * 65 + obl] = (z0 + z28 + 2.0f * a28) * sInv;
    }
    __syncthreads();

    // ob = o*32 + b
    for (int t = tid; t < NN * 64; t += 256) {
        int lob = t / NN, w = t - lob * NN;
        int ob = obt * 64 + lob;
        int o = ob >> 5, bb = ob & 31;
        out[(size_t)(bb * CO + o) * HW + h * NN + w] = Ysm[w * 65 + lob] + bias[o];
    }
}

// ---------------- launch -----------------------------------------------------
extern "C" void kernel_launch(void* const* d_in, const int* in_sizes, int n_in,
                              void* d_out, int out_size) {
    const float* x    = (const float*)d_in[0];   // [32,64,56,56]
    const float* kr   = (const float*)d_in[1];   // [128,64,56,56]
    const float* ki   = (const float*)d_in[2];   // [128,64,56,56]
    const float* bias = (const float*)d_in[3];   // [128]
    float* out = (float*)d_out;                  // [32,128,56,56]

    const int smem_fwd = HW * (int)sizeof(float)
                       + (29 * NN + NN * 30 + NN * 28) * (int)sizeof(float2);
    const int smem_mma = (128 + 64) * PADH * (int)sizeof(__half);    // 52224
    const int smem_iu  = (28 * 27 + NN * 64) * (int)sizeof(float2);
    const int smem_iv  = (28 * 27 + NV * 64) * (int)sizeof(float2) + NN * 65 * (int)sizeof(float);
    cudaFuncSetAttribute(k_fwd_fft, cudaFuncAttributeMaxDynamicSharedMemorySize, smem_fwd);
    cudaFuncSetAttribute(k_einsum_mma, cudaFuncAttributeMaxDynamicSharedMemorySize, smem_mma);
    cudaFuncSetAttribute(k_ifft_u, cudaFuncAttributeMaxDynamicSharedMemorySize, smem_iu);
    cudaFuncSetAttribute(k_ifft_v_out, cudaFuncAttributeMaxDynamicSharedMemorySize, smem_iv);

    k_init_F<<<(HW + 255) / 256, 256>>>();
    k_build_KA<<<dim3((NF + 31) / 32, OI / 32), dim3(32, 8)>>>(kr, ki);
    k_fwd_fft<<<IB, 256, smem_fwd>>>(x);
    k_einsum_mma<<<NF, 256, smem_mma>>>();
    k_ifft_u<<<dim3(64, NV), 256, smem_iu>>>();
    k_ifft_v_out<<<dim3(64, NN), 256, smem_iv>>>(bias, out);
}

// round 11
// speedup vs baseline: 3.6021x; 1.0440x over previous
#include <cuda_runtime.h>
#include <cuda_fp16.h>
#include <math_constants.h>
#include <cstdint>

// Problem constants
#define NN 56
#define HW 3136          // 56*56
#define NV 29            // rfft columns: v in [0,28]
#define NF (NN*NV)       // 1624 retained frequencies
#define NB 32            // batch
#define CI 64
#define CO 128
#define OB 4096          // CO*NB
#define IB 2048          // CI*NB
#define OI 8192          // CO*CI
#define PADH 136         // padded K stride (halfs) for mma SMEM tiles

// ---------------- scratch (device globals; no runtime allocation allowed) ----
__device__ __align__(16) float2  g_F [HW];                   // twiddles
__device__ __align__(16) __half  g_KA[(size_t)NF * 16384];   // [f][o][k=2i+c] fp16  53MB
__device__ __align__(16) __half2 g_Xf[(size_t)NF * IB];      // [f][i*32+b] cplx     13MB
__device__ __align__(16) __half2 g_Yf[(size_t)NF * OB];      // [f][o*32+b] (x 1/HW) 27MB
__device__ __align__(16) __half2 g_Z [(size_t)NF * OB];      // [h*29+v][ob]         27MB

// ---------------- 0) twiddle init -------------------------------------------
__global__ void k_init_F() {
    int idx = blockIdx.x * blockDim.x + threadIdx.x;
    if (idx < HW) {
        int j = idx / NN, k = idx % NN;
        int m = (j * k) % NN;
        float ang = -2.0f * CUDART_PI_F * (float)m / (float)NN;
        float s, c;
        sincosf(ang, &s, &c);
        g_F[idx] = make_float2(c, s);
    }
}

// ------- 1) build A tiles: g_KA[f][o][k], k=2i+c interleaved, fp16 -----------
__global__ void k_build_KA(const float* __restrict__ kr, const float* __restrict__ ki) {
    __shared__ float2 tile[32][33];     // [i_local][f_local]
    int fi0 = blockIdx.x * 32;
    int oi0 = blockIdx.y * 32;          // one o (oi0/64), i0 = oi0%64 (0 or 32)
    int tx = threadIdx.x, ty = threadIdx.y;
    int fi = fi0 + tx;
    bool valid = fi < NF;
    int u = fi / NV, v = fi - u * NV;
    int fsrc = u * NN + v;
#pragma unroll
    for (int k = 0; k < 4; k++) {
        int oi = oi0 + ty + k * 8;
        if (valid) {
            size_t src = (size_t)oi * HW + fsrc;
            tile[ty + k * 8][tx] = make_float2(kr[src], ki[src]);
        }
    }
    __syncthreads();

    int t = ty * 32 + tx;
    int f_local = t >> 3;
    int f = fi0 + f_local;
    if (f < NF) {
        int o  = oi0 >> 6;
        int i0 = oi0 & 63;
        __half2* dst = (__half2*)(g_KA + (size_t)f * 16384 + o * 128 + 2 * i0);
        int c0 = (t & 7) * 4;
#pragma unroll
        for (int r = 0; r < 4; r++) {
            int il = c0 + r;
            float2 kv = tile[il][f_local];
            dst[il] = __floats2half2_rn(kv.x, kv.y);
        }
    }
}

// ------- 2) forward rfft2 per (b,i), conjugate-pair factorized ---------------
__global__ void k_fwd_fft(const float* __restrict__ x) {
    extern __shared__ char smem[];
    float*  xs  = (float*)smem;                            // [3136]
    float2* Fs  = (float2*)(smem + HW * sizeof(float));    // [29][56]
    float2* A1  = Fs + 29 * NN;                            // [56][30]
    float2* sdm = A1 + NN * 30;                            // [56][28]

    int bi = blockIdx.x;
    int b  = bi / CI, ci = bi % CI;
    int tid = threadIdx.x;

    for (int t = tid; t < 29 * NN; t += 256) Fs[t] = g_F[t];
    for (int t = tid; t < HW; t += 256) xs[t] = x[(size_t)bi * HW + t];
    __syncthreads();

    for (int t = tid; t < NN * 28; t += 256) {
        int h = t / 28, w = t - h * 28;
        const float* xr = xs + h * NN;
        sdm[t] = (w == 0) ? make_float2(xr[0], xr[28])
                          : make_float2(xr[w] + xr[NN - w], xr[w] - xr[NN - w]);
    }
    __syncthreads();

    int lane = tid & 31;
    int grp  = tid >> 5;

    {   // stage a
        float ar[7], ai[7];
        float sgn = (lane & 1) ? -1.f : 1.f;
#pragma unroll
        for (int j = 0; j < 7; j++) {
            float2 sd0 = sdm[(grp * 7 + j) * 28];
            ar[j] = sd0.x + sgn * sd0.y;
            ai[j] = 0.f;
        }
        for (int w = 1; w < 28; w++) {
            float2 fv = Fs[w * NN + lane];
#pragma unroll
            for (int j = 0; j < 7; j++) {
                float2 sd = sdm[(grp * 7 + j) * 28 + w];
                ar[j] += fv.x * sd.x;
                ai[j] += fv.y * sd.y;
            }
        }
        if (lane < NV) {
#pragma unroll
            for (int j = 0; j < 7; j++)
                A1[(grp * 7 + j) * 30 + lane] = make_float2(ar[j], ai[j]);
        }
    }
    __syncthreads();

    {   // stage b: u-pairs via separated sums
        float Sap[4], Sbq[4], Saq[4], Sbp[4];
#pragma unroll
        for (int j = 0; j < 4; j++) { Sap[j] = Sbq[j] = Saq[j] = Sbp[j] = 0.f; }
        for (int h = 0; h < NN; h++) {
            float2 av = A1[h * 30 + lane];
#pragma unroll
            for (int j = 0; j < 4; j++) {
                int p = grp + 8 * j;
                float2 fv = Fs[(p & 31) * NN + h];   // p>28 discarded; in-bounds of smem
                Sap[j] += fv.x * av.x;
                Sbq[j] += fv.y * av.y;
                Saq[j] += fv.x * av.y;
                Sbp[j] += fv.y * av.x;
            }
        }
        if (lane < NV) {
            int col = ci * NB + b;
#pragma unroll
            for (int j = 0; j < 4; j++) {
                int p = grp + 8 * j;
                if (p <= 28) {
                    g_Xf[(size_t)(p * NV + lane) * IB + col] =
                        __floats2half2_rn(Sap[j] - Sbq[j], Saq[j] + Sbp[j]);
                    if (p != 0 && p != 28)
                        g_Xf[(size_t)((NN - p) * NV + lane) * IB + col] =
                            __floats2half2_rn(Sap[j] + Sbq[j], Saq[j] - Sbp[j]);
                }
            }
        }
    }
}

// ------- 3) mma.sync fp16 einsum, epilogue folds 1/HW, fp16 Yf out -----------
__global__ void __launch_bounds__(256, 3) k_einsum_mma() {
    extern __shared__ char smem[];
    __half* As = (__half*)smem;               // [128][PADH]
    __half* Bs = (__half*)smem + 128 * PADH;  // [64][PADH]
    int f = blockIdx.x;
    int tid = threadIdx.x;
    int wid = tid >> 5, lane = tid & 31;
    int gid = lane >> 2, tig = lane & 3;

    // load A tile (fp16, 32KB = 2048 uint4)
    {
        const uint4* Ag = (const uint4*)(g_KA + (size_t)f * 16384);
#pragma unroll 4
        for (int t = tid; t < 2048; t += 256) {
            int row = t >> 4, ch = t & 15;
            *(uint4*)(As + row * PADH + ch * 8) = Ag[t];
        }
    }
    // build B tile: row 2b = (Xr, -Xi) interleaved over k=2i+c; row 2b+1 = (Xi, Xr)
    {
        const __half2* Xg = g_Xf + (size_t)f * IB;
#pragma unroll 4
        for (int t = tid; t < 2048; t += 256) {
            __half2 xv = Xg[t];
            int i = t >> 5, b = t & 31;
            __half xr = __low2half(xv), xi = __high2half(xv);
            __half2* r0 = (__half2*)(Bs + (2 * b) * PADH + 2 * i);
            r0[0]          = __halves2half2(xr, __hneg(xi));
            *(__half2*)((__half*)r0 + PADH) = __halves2half2(xi, xr);
        }
    }
    __syncthreads();

    int m0 = wid * 16;
    float acc[8][4];
#pragma unroll
    for (int j = 0; j < 8; j++)
#pragma unroll
        for (int q = 0; q < 4; q++) acc[j][q] = 0.f;

    const __half* Ar0 = As + (m0 + gid) * PADH + 2 * tig;
    const __half* Ar1 = Ar0 + 8 * PADH;
    const __half* Br  = Bs + gid * PADH + 2 * tig;

#pragma unroll
    for (int kc = 0; kc < 8; kc++) {
        int k0 = kc * 16;
        uint32_t a0 = *(const uint32_t*)(Ar0 + k0);
        uint32_t a1 = *(const uint32_t*)(Ar1 + k0);
        uint32_t a2 = *(const uint32_t*)(Ar0 + k0 + 8);
        uint32_t a3 = *(const uint32_t*)(Ar1 + k0 + 8);
#pragma unroll
        for (int j = 0; j < 8; j++) {
            uint32_t b0 = *(const uint32_t*)(Br + j * 8 * PADH + k0);
            uint32_t b1 = *(const uint32_t*)(Br + j * 8 * PADH + k0 + 8);
            asm volatile(
                "mma.sync.aligned.m16n8k16.row.col.f32.f16.f16.f32 "
                "{%0,%1,%2,%3}, {%4,%5,%6,%7}, {%8,%9}, {%0,%1,%2,%3};"
                : "+f"(acc[j][0]), "+f"(acc[j][1]), "+f"(acc[j][2]), "+f"(acc[j][3])
                : "r"(a0), "r"(a1), "r"(a2), "r"(a3), "r"(b0), "r"(b1));
        }
    }

    // epilogue: scale by 1/HW (ifft normalization) and store fp16
    const float sInv = 1.0f / (float)HW;
    __half2* Yf = g_Yf + (size_t)f * OB;
#pragma unroll
    for (int j = 0; j < 8; j++) {
        int b = 4 * j + tig;
        Yf[(m0 + gid) * NB + b]     = __floats2half2_rn(acc[j][0] * sInv, acc[j][1] * sInv);
        Yf[(m0 + gid + 8) * NB + b] = __floats2half2_rn(acc[j][2] * sInv, acc[j][3] * sInv);
    }
}

// ------- 4) inverse over u, double conjugate-pair (fp16 I/O, fp32 math) ------
__global__ void k_ifft_u() {
    extern __shared__ char smem[];
    float2* Fc  = (float2*)smem;      // [28][27]
    float2* Ysm = Fc + 28 * 27;       // [56][64]
    int v   = blockIdx.y;
    int obt = blockIdx.x;
    int tid = threadIdx.x;
    int wg  = tid >> 6;
    int obl = tid & 63;

    for (int t = tid; t < 28 * 27; t += 256) {
        int s = t / 27, u = t - s * 27 + 1;
        if (s < 27) {
            float2 f = g_F[(s + 1) * NN + u];
            Fc[t] = make_float2(f.x, -f.y);
        } else {
            Fc[t] = make_float2(0.f, 0.f);
        }
    }
    for (int t = tid; t < NN * 64; t += 256) {
        int uu = t >> 6, oo = t & 63;
        Ysm[t] = __half22float2(g_Yf[(size_t)(uu * NV + v) * OB + obt * 64 + oo]);
    }
    __syncthreads();

    float2 Y0  = Ysm[obl];
    float2 Y28 = Ysm[28 * 64 + obl];

    float S1[7], S2[7], S3[7], S4[7];
#pragma unroll
    for (int j = 0; j < 7; j++) { S1[j] = S2[j] = S3[j] = S4[j] = 0.f; }

#pragma unroll 3
    for (int up = 1; up < 28; up++) {
        float2 Yu = Ysm[up * 64 + obl];
        float2 Ym = Ysm[(NN - up) * 64 + obl];
        float Px = Yu.x + Ym.x, Py = Yu.y + Ym.y;
        float Mx = Yu.x - Ym.x, My = Yu.y - Ym.y;
#pragma unroll
        for (int j = 0; j < 7; j++) {
            float2 c = Fc[(wg * 7 + j) * 27 + up - 1];
            S1[j] += c.x * Px;
            S2[j] += c.y * My;
            S3[j] += c.x * Py;
            S4[j] += c.y * Mx;
        }
    }

    int ob = obt * 64 + obl;
#pragma unroll
    for (int j = 0; j < 7; j++) {
        int s = wg * 7 + j;
        if (s < 27) {
            int h = s + 1;
            float sg = (h & 1) ? -1.f : 1.f;
            float bx = Y0.x + sg * Y28.x, by = Y0.y + sg * Y28.y;
            g_Z[(size_t)(h * NV + v) * OB + ob] =
                __floats2half2_rn(bx + S1[j] - S2[j], by + S3[j] + S4[j]);
            g_Z[(size_t)((NN - h) * NV + v) * OB + ob] =
                __floats2half2_rn(bx + S1[j] + S2[j], by + S3[j] - S4[j]);
        }
    }
    if (wg == 3) {
        float2 a0 = make_float2(Y0.x + Y28.x, Y0.y + Y28.y);
        float2 a28 = a0;
        for (int up = 1; up < 28; up++) {
            float2 Yu = Ysm[up * 64 + obl];
            float2 Ym = Ysm[(NN - up) * 64 + obl];
            float Px = Yu.x + Ym.x, Py = Yu.y + Ym.y;
            float sg = (up & 1) ? -1.f : 1.f;
            a0.x += Px;        a0.y += Py;
            a28.x += sg * Px;  a28.y += sg * Py;
        }
        g_Z[(size_t)(0 * NV + v) * OB + ob]  = __floats2half2_rn(a0.x, a0.y);
        g_Z[(size_t)(28 * NV + v) * OB + ob] = __floats2half2_rn(a28.x, a28.y);
    }
}

// ------- 5) Hermitian inverse over v, w-paired, + bias + final layout --------
__global__ void k_ifft_v_out(const float* __restrict__ bias, float* __restrict__ out) {
    extern __shared__ char smem[];
    float2* FsC = (float2*)smem;               // [28][27]
    float2* Zsm = FsC + 28 * 27;               // [29][64]
    float*  Ysm = (float*)(Zsm + NV * 64);     // [56][65]
    int h   = blockIdx.y;
    int obt = blockIdx.x;
    int tid = threadIdx.x;
    int wg  = tid >> 6;
    int obl = tid & 63;

    for (int t = tid; t < 28 * 27; t += 256) {
        int s = t / 27, v = t - s * 27 + 1;
        if (s < 27) {
            float2 f = g_F[(s + 1) * NN + v];
            FsC[t] = make_float2(f.x, -f.y);
        } else {
            FsC[t] = make_float2(0.f, 0.f);
        }
    }
    for (int t = tid; t < NV * 64; t += 256) {
        int v = t >> 6, oo = t & 63;
        Zsm[t] = __half22float2(g_Z[(size_t)(h * NV + v) * OB + obt * 64 + oo]);
    }
    __syncthreads();

    float Sc[7], Ss[7];
#pragma unroll
    for (int j = 0; j < 7; j++) { Sc[j] = Ss[j] = 0.f; }

#pragma unroll 3
    for (int v = 1; v < 28; v++) {
        float2 z = Zsm[v * 64 + obl];
#pragma unroll
        for (int j = 0; j < 7; j++) {
            float2 c = FsC[(wg * 7 + j) * 27 + v - 1];
            Sc[j] += z.x * c.x;
            Ss[j] += z.y * c.y;
        }
    }

    float z0  = Zsm[obl].x;
    float z28 = Zsm[28 * 64 + obl].x;
#pragma unroll
    for (int j = 0; j < 7; j++) {
        int s = wg * 7 + j;
        if (s < 27) {
            int w = s + 1;
            float par = (w & 1) ? -z28 : z28;
            float base = z0 + par;
            Ysm[w * 65 + obl]        = base + 2.0f * (Sc[j] - Ss[j]);
            Ysm[(NN - w) * 65 + obl] = base + 2.0f * (Sc[j] + Ss[j]);
        }
    }
    if (wg == 3) {
        float a0 = 0.f, a28 = 0.f;
        for (int v = 1; v < 28; v++) {
            float zr = Zsm[v * 64 + obl].x;
            a0 += zr;
            a28 += (v & 1) ? -zr : zr;
        }
        Ysm[0 * 65 + obl]  = z0 + z28 + 2.0f * a0;
        Ysm[28 * 65 + obl] = z0 + z28 + 2.0f * a28;
    }
    __syncthreads();

    // ob = o*32 + b
    for (int t = tid; t < NN * 64; t += 256) {
        int lob = t / NN, w = t - lob * NN;
        int ob = obt * 64 + lob;
        int o = ob >> 5, bb = ob & 31;
        out[(size_t)(bb * CO + o) * HW + h * NN + w] = Ysm[w * 65 + lob] + bias[o];
    }
}

// ---------------- launch -----------------------------------------------------
extern "C" void kernel_launch(void* const* d_in, const int* in_sizes, int n_in,
                              void* d_out, int out_size) {
    const float* x    = (const float*)d_in[0];   // [32,64,56,56]
    const float* kr   = (const float*)d_in[1];   // [128,64,56,56]
    const float* ki   = (const float*)d_in[2];   // [128,64,56,56]
    const float* bias = (const float*)d_in[3];   // [128]
    float* out = (float*)d_out;                  // [32,128,56,56]

    const int smem_fwd = HW * (int)sizeof(float)
                       + (29 * NN + NN * 30 + NN * 28) * (int)sizeof(float2);
    const int smem_mma = (128 + 64) * PADH * (int)sizeof(__half);    // 52224
    const int smem_iu  = (28 * 27 + NN * 64) * (int)sizeof(float2);
    const int smem_iv  = (28 * 27 + NV * 64) * (int)sizeof(float2) + NN * 65 * (int)sizeof(float);
    cudaFuncSetAttribute(k_fwd_fft, cudaFuncAttributeMaxDynamicSharedMemorySize, smem_fwd);
    cudaFuncSetAttribute(k_einsum_mma, cudaFuncAttributeMaxDynamicSharedMemorySize, smem_mma);
    cudaFuncSetAttribute(k_ifft_u, cudaFuncAttributeMaxDynamicSharedMemorySize, smem_iu);
    cudaFuncSetAttribute(k_ifft_v_out, cudaFuncAttributeMaxDynamicSharedMemorySize, smem_iv);

    k_init_F<<<(HW + 255) / 256, 256>>>();
    k_build_KA<<<dim3((NF + 31) / 32, OI / 32), dim3(32, 8)>>>(kr, ki);
    k_fwd_fft<<<IB, 256, smem_fwd>>>(x);
    k_einsum_mma<<<NF, 256, smem_mma>>>();
    k_ifft_u<<<dim3(64, NV), 256, smem_iu>>>();
    k_ifft_v_out<<<dim3(64, NN), 256, smem_iv>>>(bias, out);
}

// round 15
// speedup vs baseline: 3.8485x; 1.0684x over previous
#include <cuda_runtime.h>
#include <cuda_fp16.h>
#include <math_constants.h>
#include <cstdint>

// Problem constants
#define NN 56
#define HW 3136          // 56*56
#define NV 29            // rfft columns: v in [0,28]
#define NF (NN*NV)       // 1624 retained frequencies
#define NB 32            // batch
#define CI 64
#define CO 128
#define OB 4096          // CO*NB
#define IB 2048          // CI*NB
#define OI 8192          // CO*CI
#define PADH 136         // padded K stride (halfs) for einsum mma tiles
#define PKA 122          // padded K stride for ifft_u mma (112 used)
#define PKV 74           // padded K stride for ifft_v mma (58 used, 64 read)

// ---------------- scratch (device globals; no runtime allocation allowed) ----
__device__ __align__(16) float2  g_F [HW];                   // twiddles
__device__ __align__(16) __half  g_KA[(size_t)NF * 16384];   // [f][o][k=2i+c] fp16  53MB
__device__ __align__(16) __half2 g_Xf[(size_t)NF * IB];      // [f][i*32+b] cplx     13MB
__device__ __align__(16) __half2 g_Yf[(size_t)NF * OB];      // [f][o*32+b] (x 1/HW) 27MB
__device__ __align__(16) __half2 g_Z [(size_t)NF * OB];      // [h*29+v][ob]         27MB
__device__ __align__(16) __half  g_Au[64 * PKA];             // ifft_u twiddle A
__device__ __align__(16) __half  g_Av[64 * PKV];             // ifft_v twiddle A

// ---------------- 0) twiddle init -------------------------------------------
__global__ void k_init_F() {
    int idx = blockIdx.x * blockDim.x + threadIdx.x;
    if (idx < HW) {
        int j = idx / NN, k = idx % NN;
        int m = (j * k) % NN;
        float ang = -2.0f * CUDART_PI_F * (float)m / (float)NN;
        float s, c;
        sincosf(ang, &s, &c);
        g_F[idx] = make_float2(c, s);
    }
}

// ------- 0b) constant A matrices for the two inverse-transform MMAs ----------
// g_Au[h][2u] = cos(2pi h u/56), [2u+1] = sin(2pi h u/56)   (= conjF), h<56,u<56
// g_Av[w][2v]: v=0 -> 1; v=28 -> (-1)^w; else 2cos(2pi v w/56)
// g_Av[w][2v+1]: v in {0,28} -> 0; else -2 sin(2pi v w/56)
__global__ void k_init_A() {
    int s = blockIdx.x * blockDim.x + threadIdx.x;
    if (s < 64 * PKA) {
        int h = s / PKA, c = s - h * PKA;
        float val = 0.f;
        if (h < NN && c < 112) {
            int u = c >> 1;
            int m = (h * u) % NN;
            float ang = 2.0f * CUDART_PI_F * (float)m / (float)NN;
            val = (c & 1) ? sinf(ang) : cosf(ang);
        }
        g_Au[s] = __float2half(val);
    } else if (s < 64 * PKA + 64 * PKV) {
        int s2 = s - 64 * PKA;
        int w = s2 / PKV, c = s2 - w * PKV;
        float val = 0.f;
        if (w < NN && c < 58) {
            int v = c >> 1;
            if (v == 0)       val = (c & 1) ? 0.f : 1.f;
            else if (v == 28) val = (c & 1) ? 0.f : ((w & 1) ? -1.f : 1.f);
            else {
                int m = (v * w) % NN;
                float ang = 2.0f * CUDART_PI_F * (float)m / (float)NN;
                val = (c & 1) ? -2.0f * sinf(ang) : 2.0f * cosf(ang);
            }
        }
        g_Av[s2] = __float2half(val);
    }
}

// ------- 1) build A tiles: g_KA[f][o][k], k=2i+c interleaved, fp16 -----------
__global__ void k_build_KA(const float* __restrict__ kr, const float* __restrict__ ki) {
    __shared__ float2 tile[32][33];     // [i_local][f_local]
    int fi0 = blockIdx.x * 32;
    int oi0 = blockIdx.y * 32;          // one o (oi0/64), i0 = oi0%64 (0 or 32)
    int tx = threadIdx.x, ty = threadIdx.y;
    int fi = fi0 + tx;
    bool valid = fi < NF;
    int u = fi / NV, v = fi - u * NV;
    int fsrc = u * NN + v;
#pragma unroll
    for (int k = 0; k < 4; k++) {
        int oi = oi0 + ty + k * 8;
        if (valid) {
            size_t src = (size_t)oi * HW + fsrc;
            tile[ty + k * 8][tx] = make_float2(kr[src], ki[src]);
        }
    }
    __syncthreads();

    int t = ty * 32 + tx;
    int f_local = t >> 3;
    int f = fi0 + f_local;
    if (f < NF) {
        int o  = oi0 >> 6;
        int i0 = oi0 & 63;
        __half2* dst = (__half2*)(g_KA + (size_t)f * 16384 + o * 128 + 2 * i0);
        int c0 = (t & 7) * 4;
#pragma unroll
        for (int r = 0; r < 4; r++) {
            int il = c0 + r;
            float2 kv = tile[il][f_local];
            dst[il] = __floats2half2_rn(kv.x, kv.y);
        }
    }
}

// ------- 2) forward rfft2 per (b,i), conjugate-pair factorized ---------------
__global__ void k_fwd_fft(const float* __restrict__ x) {
    extern __shared__ char smem[];
    float*  xs  = (float*)smem;                            // [3136]
    float2* Fs  = (float2*)(smem + HW * sizeof(float));    // [29][56]
    float2* A1  = Fs + 29 * NN;                            // [56][30]
    float2* sdm = A1 + NN * 30;                            // [56][28]

    int bi = blockIdx.x;
    int b  = bi / CI, ci = bi % CI;
    int tid = threadIdx.x;

    for (int t = tid; t < 29 * NN; t += 256) Fs[t] = g_F[t];
    for (int t = tid; t < HW; t += 256) xs[t] = x[(size_t)bi * HW + t];
    __syncthreads();

    for (int t = tid; t < NN * 28; t += 256) {
        int h = t / 28, w = t - h * 28;
        const float* xr = xs + h * NN;
        sdm[t] = (w == 0) ? make_float2(xr[0], xr[28])
                          : make_float2(xr[w] + xr[NN - w], xr[w] - xr[NN - w]);
    }
    __syncthreads();

    int lane = tid & 31;
    int grp  = tid >> 5;

    {   // stage a
        float ar[7], ai[7];
        float sgn = (lane & 1) ? -1.f : 1.f;
#pragma unroll
        for (int j = 0; j < 7; j++) {
            float2 sd0 = sdm[(grp * 7 + j) * 28];
            ar[j] = sd0.x + sgn * sd0.y;
            ai[j] = 0.f;
        }
        for (int w = 1; w < 28; w++) {
            float2 fv = Fs[w * NN + lane];
#pragma unroll
            for (int j = 0; j < 7; j++) {
                float2 sd = sdm[(grp * 7 + j) * 28 + w];
                ar[j] += fv.x * sd.x;
                ai[j] += fv.y * sd.y;
            }
        }
        if (lane < NV) {
#pragma unroll
            for (int j = 0; j < 7; j++)
                A1[(grp * 7 + j) * 30 + lane] = make_float2(ar[j], ai[j]);
        }
    }
    __syncthreads();

    {   // stage b: u-pairs via separated sums
        float Sap[4], Sbq[4], Saq[4], Sbp[4];
#pragma unroll
        for (int j = 0; j < 4; j++) { Sap[j] = Sbq[j] = Saq[j] = Sbp[j] = 0.f; }
        for (int h = 0; h < NN; h++) {
            float2 av = A1[h * 30 + lane];
#pragma unroll
            for (int j = 0; j < 4; j++) {
                int p = grp + 8 * j;
                float2 fv = Fs[(p & 31) * NN + h];   // p>28 discarded; in-bounds of smem
                Sap[j] += fv.x * av.x;
                Sbq[j] += fv.y * av.y;
                Saq[j] += fv.x * av.y;
                Sbp[j] += fv.y * av.x;
            }
        }
        if (lane < NV) {
            int col = ci * NB + b;
#pragma unroll
            for (int j = 0; j < 4; j++) {
                int p = grp + 8 * j;
                if (p <= 28) {
                    g_Xf[(size_t)(p * NV + lane) * IB + col] =
                        __floats2half2_rn(Sap[j] - Sbq[j], Saq[j] + Sbp[j]);
                    if (p != 0 && p != 28)
                        g_Xf[(size_t)((NN - p) * NV + lane) * IB + col] =
                            __floats2half2_rn(Sap[j] + Sbq[j], Saq[j] - Sbp[j]);
                }
            }
        }
    }
}

// ------- 3) mma.sync fp16 einsum, epilogue folds 1/HW, fp16 Yf out -----------
__global__ void __launch_bounds__(256, 3) k_einsum_mma() {
    extern __shared__ char smem[];
    __half* As = (__half*)smem;               // [128][PADH]
    __half* Bs = (__half*)smem + 128 * PADH;  // [64][PADH]
    int f = blockIdx.x;
    int tid = threadIdx.x;
    int wid = tid >> 5, lane = tid & 31;
    int gid = lane >> 2, tig = lane & 3;

    {
        const uint4* Ag = (const uint4*)(g_KA + (size_t)f * 16384);
#pragma unroll 4
        for (int t = tid; t < 2048; t += 256) {
            int row = t >> 4, ch = t & 15;
            *(uint4*)(As + row * PADH + ch * 8) = Ag[t];
        }
    }
    {
        const __half2* Xg = g_Xf + (size_t)f * IB;
#pragma unroll 4
        for (int t = tid; t < 2048; t += 256) {
            __half2 xv = Xg[t];
            int i = t >> 5, b = t & 31;
            __half xr = __low2half(xv), xi = __high2half(xv);
            __half2* r0 = (__half2*)(Bs + (2 * b) * PADH + 2 * i);
            r0[0]          = __halves2half2(xr, __hneg(xi));
            *(__half2*)((__half*)r0 + PADH) = __halves2half2(xi, xr);
        }
    }
    __syncthreads();

    int m0 = wid * 16;
    float acc[8][4];
#pragma unroll
    for (int j = 0; j < 8; j++)
#pragma unroll
        for (int q = 0; q < 4; q++) acc[j][q] = 0.f;

    const __half* Ar0 = As + (m0 + gid) * PADH + 2 * tig;
    const __half* Ar1 = Ar0 + 8 * PADH;
    const __half* Br  = Bs + gid * PADH + 2 * tig;

#pragma unroll
    for (int kc = 0; kc < 8; kc++) {
        int k0 = kc * 16;
        uint32_t a0 = *(const uint32_t*)(Ar0 + k0);
        uint32_t a1 = *(const uint32_t*)(Ar1 + k0);
        uint32_t a2 = *(const uint32_t*)(Ar0 + k0 + 8);
        uint32_t a3 = *(const uint32_t*)(Ar1 + k0 + 8);
#pragma unroll
        for (int j = 0; j < 8; j++) {
            uint32_t b0 = *(const uint32_t*)(Br + j * 8 * PADH + k0);
            uint32_t b1 = *(const uint32_t*)(Br + j * 8 * PADH + k0 + 8);
            asm volatile(
                "mma.sync.aligned.m16n8k16.row.col.f32.f16.f16.f32 "
                "{%0,%1,%2,%3}, {%4,%5,%6,%7}, {%8,%9}, {%0,%1,%2,%3};"
                : "+f"(acc[j][0]), "+f"(acc[j][1]), "+f"(acc[j][2]), "+f"(acc[j][3])
                : "r"(a0), "r"(a1), "r"(a2), "r"(a3), "r"(b0), "r"(b1));
        }
    }

    const float sInv = 1.0f / (float)HW;
    __half2* Yf = g_Yf + (size_t)f * OB;
#pragma unroll
    for (int j = 0; j < 8; j++) {
        int b = 4 * j + tig;
        Yf[(m0 + gid) * NB + b]     = __floats2half2_rn(acc[j][0] * sInv, acc[j][1] * sInv);
        Yf[(m0 + gid + 8) * NB + b] = __floats2half2_rn(acc[j][2] * sInv, acc[j][3] * sInv);
    }
}

// ------- 4) mma inverse over u: Z[h,ob] = sum_u conjF[h,u] Y[u,ob], per v ----
// A = g_Au [64][PKA] (rows 56..63 zero), B built from Yf, M=64 K=112 N=128
__global__ void __launch_bounds__(256, 3) k_ifft_u_mma() {
    extern __shared__ char smem[];
    __half* As = (__half*)smem;               // [64][PKA]
    __half* Bs = As + 64 * PKA;               // [128][PKA]
    int v = blockIdx.y, obt = blockIdx.x;
    int tid = threadIdx.x;
    int wid = tid >> 5, lane = tid & 31;
    int gid = lane >> 2, tig = lane & 3;
    int warpm = wid & 3, warpn = wid >> 2;

    {
        const uint4* Ag = (const uint4*)g_Au;
        uint4* Ad = (uint4*)As;
#pragma unroll 4
        for (int t = tid; t < (64 * PKA) / 8; t += 256) Ad[t] = Ag[t];
    }
    // build B: row 2ob = (Yr, -Yi) over k=2u+c; row 2ob+1 = (Yi, Yr)
    for (int t = tid; t < NN * 64; t += 256) {
        int u = t >> 6, obl = t & 63;
        __half2 y = g_Yf[(size_t)(u * NV + v) * OB + obt * 64 + obl];
        __half yr = __low2half(y), yi = __high2half(y);
        *(__half2*)(Bs + (2 * obl) * PKA + 2 * u)     = __halves2half2(yr, __hneg(yi));
        *(__half2*)(Bs + (2 * obl + 1) * PKA + 2 * u) = __halves2half2(yi, yr);
    }
    __syncthreads();

    int m0 = warpm * 16, n0 = warpn * 64;
    float acc[8][4];
#pragma unroll
    for (int j = 0; j < 8; j++)
#pragma unroll
        for (int q = 0; q < 4; q++) acc[j][q] = 0.f;

    const __half* Ar0 = As + (m0 + gid) * PKA + 2 * tig;
    const __half* Ar1 = Ar0 + 8 * PKA;
    const __half* Br  = Bs + (n0 + gid) * PKA + 2 * tig;

#pragma unroll
    for (int kc = 0; kc < 7; kc++) {
        int k0 = kc * 16;
        uint32_t a0 = *(const uint32_t*)(Ar0 + k0);
        uint32_t a1 = *(const uint32_t*)(Ar1 + k0);
        uint32_t a2 = *(const uint32_t*)(Ar0 + k0 + 8);
        uint32_t a3 = *(const uint32_t*)(Ar1 + k0 + 8);
#pragma unroll
        for (int j = 0; j < 8; j++) {
            uint32_t b0 = *(const uint32_t*)(Br + j * 8 * PKA + k0);
            uint32_t b1 = *(const uint32_t*)(Br + j * 8 * PKA + k0 + 8);
            asm volatile(
                "mma.sync.aligned.m16n8k16.row.col.f32.f16.f16.f32 "
                "{%0,%1,%2,%3}, {%4,%5,%6,%7}, {%8,%9}, {%0,%1,%2,%3};"
                : "+f"(acc[j][0]), "+f"(acc[j][1]), "+f"(acc[j][2]), "+f"(acc[j][3])
                : "r"(a0), "r"(a1), "r"(a2), "r"(a3), "r"(b0), "r"(b1));
        }
    }

    // C frag: cols 2q/2q+1 = real/imag of complex ob index q = warpn*32+4j+tig
    int h0 = m0 + gid, h1 = h0 + 8;
#pragma unroll
    for (int j = 0; j < 8; j++) {
        int q = warpn * 32 + 4 * j + tig;
        g_Z[(size_t)(h0 * NV + v) * OB + obt * 64 + q] =
            __floats2half2_rn(acc[j][0], acc[j][1]);
        if (h1 < NN)
            g_Z[(size_t)(h1 * NV + v) * OB + obt * 64 + q] =
                __floats2half2_rn(acc[j][2], acc[j][3]);
    }
}

// ------- 5) mma Hermitian inverse over v + bias + final layout, per h --------
// A2 = g_Av [64][PKV]; B from Z; M=64(w) K=64 N=64(ob); real output
__global__ void __launch_bounds__(256, 4) k_ifft_v_mma(const float* __restrict__ bias,
                                                       float* __restrict__ out) {
    extern __shared__ char smem[];
    __half* As = (__half*)smem;               // [64][PKV]
    __half* Bs = As + 64 * PKV;               // [64][PKV]
    int h = blockIdx.y, obt = blockIdx.x;
    int tid = threadIdx.x;
    int wid = tid >> 5, lane = tid & 31;
    int gid = lane >> 2, tig = lane & 3;
    int warpm = wid & 3, warpn = wid >> 2;

    {
        const uint4* Ag = (const uint4*)g_Av;
#pragma unroll 2
        for (int t = tid; t < (64 * PKV) / 8; t += 256) ((uint4*)As)[t] = Ag[t];
    }
    // zero pad cols 58..63 of B (read by last k-chunk)
    for (int t = tid; t < 64 * 3; t += 256) {
        int c = t >> 6, obl = t & 63;
        *(__half2*)(Bs + obl * PKV + 58 + 2 * c) = __float2half2_rn(0.f);
    }
    // build B: B[ob][2v]=Zr, [2v+1]=Zi
    for (int t = tid; t < NV * 64; t += 256) {
        int vv = t >> 6, obl = t & 63;
        *(__half2*)(Bs + obl * PKV + 2 * vv) =
            g_Z[(size_t)(h * NV + vv) * OB + obt * 64 + obl];
    }
    __syncthreads();

    int m0 = warpm * 16, n0 = warpn * 32;
    float acc[4][4];
#pragma unroll
    for (int j = 0; j < 4; j++)
#pragma unroll
        for (int q = 0; q < 4; q++) acc[j][q] = 0.f;

    const __half* Ar0 = As + (m0 + gid) * PKV + 2 * tig;
    const __half* Ar1 = Ar0 + 8 * PKV;
    const __half* Br  = Bs + (n0 + gid) * PKV + 2 * tig;

#pragma unroll
    for (int kc = 0; kc < 4; kc++) {
        int k0 = kc * 16;
        uint32_t a0 = *(const uint32_t*)(Ar0 + k0);
        uint32_t a1 = *(const uint32_t*)(Ar1 + k0);
        uint32_t a2 = *(const uint32_t*)(Ar0 + k0 + 8);
        uint32_t a3 = *(const uint32_t*)(Ar1 + k0 + 8);
#pragma unroll
        for (int j = 0; j < 4; j++) {
            uint32_t b0 = *(const uint32_t*)(Br + j * 8 * PKV + k0);
            uint32_t b1 = *(const uint32_t*)(Br + j * 8 * PKV + k0 + 8);
            asm volatile(
                "mma.sync.aligned.m16n8k16.row.col.f32.f16.f16.f32 "
                "{%0,%1,%2,%3}, {%4,%5,%6,%7}, {%8,%9}, {%0,%1,%2,%3};"
                : "+f"(acc[j][0]), "+f"(acc[j][1]), "+f"(acc[j][2]), "+f"(acc[j][3])
                : "r"(a0), "r"(a1), "r"(a2), "r"(a3), "r"(b0), "r"(b1));
        }
    }

    // C frag: rows w0/w1, cols 8j+2tig (+1); col even so col and col+1 share o
    int w0 = m0 + gid, w1 = w0 + 8;
#pragma unroll
    for (int j = 0; j < 4; j++) {
        int col = n0 + 8 * j + 2 * tig;       // even
        int ob = obt * 64 + col;
        int o = ob >> 5, bb = ob & 31;        // ob = o*32+b, b even
        float bv = bias[o];
        size_t base0 = (size_t)(bb * CO + o) * HW + h * NN;
        size_t base1 = (size_t)((bb + 1) * CO + o) * HW + h * NN;
        out[base0 + w0] = acc[j][0] + bv;
        out[base1 + w0] = acc[j][1] + bv;
        if (w1 < NN) {
            out[base0 + w1] = acc[j][2] + bv;
            out[base1 + w1] = acc[j][3] + bv;
        }
    }
}

// ---------------- launch -----------------------------------------------------
extern "C" void kernel_launch(void* const* d_in, const int* in_sizes, int n_in,
                              void* d_out, int out_size) {
    const float* x    = (const float*)d_in[0];   // [32,64,56,56]
    const float* kr   = (const float*)d_in[1];   // [128,64,56,56]
    const float* ki   = (const float*)d_in[2];   // [128,64,56,56]
    const float* bias = (const float*)d_in[3];   // [128]
    float* out = (float*)d_out;                  // [32,128,56,56]

    const int smem_fwd = HW * (int)sizeof(float)
                       + (29 * NN + NN * 30 + NN * 28) * (int)sizeof(float2);
    const int smem_mma = (128 + 64) * PADH * (int)sizeof(__half);    // 52224
    const int smem_iu  = (64 + 128) * PKA * (int)sizeof(__half);     // 46848
    const int smem_iv  = (64 + 64) * PKV * (int)sizeof(__half);      // 18944
    cudaFuncSetAttribute(k_fwd_fft, cudaFuncAttributeMaxDynamicSharedMemorySize, smem_fwd);
    cudaFuncSetAttribute(k_einsum_mma, cudaFuncAttributeMaxDynamicSharedMemorySize, smem_mma);
    cudaFuncSetAttribute(k_ifft_u_mma, cudaFuncAttributeMaxDynamicSharedMemorySize, smem_iu);
    cudaFuncSetAttribute(k_ifft_v_mma, cudaFuncAttributeMaxDynamicSharedMemorySize, smem_iv);

    k_init_F<<<(HW + 255) / 256, 256>>>();
    k_init_A<<<(64 * PKA + 64 * PKV + 255) / 256, 256>>>();
    k_build_KA<<<dim3((NF + 31) / 32, OI / 32), dim3(32, 8)>>>(kr, ki);
    k_fwd_fft<<<IB, 256, smem_fwd>>>(x);
    k_einsum_mma<<<NF, 256, smem_mma>>>();
    k_ifft_u_mma<<<dim3(64, NV), 256, smem_iu>>>();
    k_ifft_v_mma<<<dim3(64, NN), 256, smem_iv>>>(bias, out);
}